// round 8
// baseline (speedup 1.0000x reference)
#include <cuda_runtime.h>
#include <cuda_fp16.h>
#include <cstdint>

// Problem constants
#define TPc   4
#define WSZ   16
#define B_    8
#define F_    256
#define K_    64
#define EDv   256
#define NWIN  2048
#define NPAIR 1024
#define WTYPES 256
#define GRID_P 152     // persistent CTAs (GB300: 152 SMs, 1 CTA/SM)

// Shared memory layout (byte offsets)
//  buf[2]:  2 x 64 rows x 528B  (xn -> y per window-group)
//  Wsm:     256 rows x 528B     (full fp16 Wp, staged once)
//  As:      64 rows x 144B      (A_w fp16, staged per pair)
#define OFF_BUF1 33792
#define OFF_WSM  67584
#define OFF_AS   202752
#define OFF_MU   211968
#define OFF_RS   212480
#define OFF_GR   212992
#define OFF_GS   213504
#define OFF_BS   214528
#define OFF_BPS  215552
#define SMEM_REQ 216576

#define BUF_S32 132       // buf row stride in b32 (264 halfs); 528B = 33x16B (odd)
#define BUF_SB  528
#define WSM_SB  528       // Wsm row stride: 256 halfs + 16B pad (33x16B, odd)
#define A_SB    144       // As row stride: 64 halfs + 16B pad (9x16B, odd)

// Precomputed fp16 operands (device globals: no allocation)
__device__ __half g_Wh[EDv * EDv];            // Wp as fp16, row-major [o][k]
__device__ __half g_Ah[WTYPES * 64 * 64];     // A = deg@eb as fp16

// ---------------------------------------------------------------------------
// Prep kernel 1: Wp -> fp16
// ---------------------------------------------------------------------------
__global__ __launch_bounds__(256) void convert_Wp_kernel(const float* __restrict__ Wp)
{
    int i = blockIdx.x * 256 + threadIdx.x;
    g_Wh[i] = __float2half_rn(Wp[i]);
}

// ---------------------------------------------------------------------------
// Prep kernel 2: A[w] = deg[w] @ eb[w] (fp32 FFMA), stored as fp16
// ---------------------------------------------------------------------------
__global__ __launch_bounds__(256) void compute_A_kernel(
    const float* __restrict__ deg, const float* __restrict__ eb)
{
    __shared__ float Ds[64][64];
    __shared__ float Es[64][68];
    int w = blockIdx.x, tid = threadIdx.x;
    const float* D = deg + (size_t)w * 4096;
    const float* E = eb  + (size_t)w * 4096;
    for (int idx = tid; idx < 4096; idx += 256) {
        Ds[idx >> 6][idx & 63] = D[idx];
        Es[idx >> 6][idx & 63] = E[idx];
    }
    __syncthreads();
    int p  = tid >> 2;
    int q0 = (tid & 3) * 16;
    float acc[16];
#pragma unroll
    for (int j = 0; j < 16; j++) acc[j] = 0.f;
    for (int k = 0; k < 64; k++) {
        float a = Ds[p][k];
#pragma unroll
        for (int j = 0; j < 16; j++) acc[j] = fmaf(a, Es[k][q0 + j], acc[j]);
    }
    __half* Aout = g_Ah + (size_t)w * 4096 + p * 64 + q0;
#pragma unroll
    for (int j = 0; j < 16; j++) Aout[j] = __float2half_rn(acc[j]);
}

// ---------------------------------------------------------------------------
// mma / ldmatrix helpers
// ---------------------------------------------------------------------------
__device__ __forceinline__ uint32_t smem_u32(const void* p) {
    uint32_t a;
    asm("{ .reg .u64 t; cvta.to.shared.u64 t, %1; cvt.u32.u64 %0, t; }" : "=r"(a) : "l"(p));
    return a;
}

#define LDSM4(r0, r1, r2, r3, addr) \
    asm volatile("ldmatrix.sync.aligned.m8n8.x4.shared.b16 {%0,%1,%2,%3}, [%4];" \
                 : "=r"(r0), "=r"(r1), "=r"(r2), "=r"(r3) : "r"(addr))
#define LDSM4T(r0, r1, r2, r3, addr) \
    asm volatile("ldmatrix.sync.aligned.m8n8.x4.trans.shared.b16 {%0,%1,%2,%3}, [%4];" \
                 : "=r"(r0), "=r"(r1), "=r"(r2), "=r"(r3) : "r"(addr))

__device__ __forceinline__ void hmma(float c[4], const uint32_t a[4],
                                     uint32_t b0, uint32_t b1) {
    asm volatile(
        "mma.sync.aligned.m16n8k16.row.col.f32.f16.f16.f32 "
        "{%0,%1,%2,%3}, {%4,%5,%6,%7}, {%8,%9}, {%0,%1,%2,%3};"
        : "+f"(c[0]), "+f"(c[1]), "+f"(c[2]), "+f"(c[3])
        : "r"(a[0]), "r"(a[1]), "r"(a[2]), "r"(a[3]), "r"(b0), "r"(b1));
}

__device__ __forceinline__ void group_bar(int g) {
    asm volatile("bar.sync %0, 256;" :: "r"(g + 1) : "memory");
}

// ---------------------------------------------------------------------------
// Persistent fused kernel: 152 CTAs x 512 threads (2 window-groups of 8 warps).
// Wp staged to smem ONCE per CTA; loop over window-pairs:
//   As stage + LN pass1 -> LN pass2 -> GEMM1 (16 k-steps, no inner barriers)
//   -> y in buf -> GEMM2 -> direct scatter (window_reverse)
// ---------------------------------------------------------------------------
__global__ __launch_bounds__(512, 1) void fused_persist(
    const float* __restrict__ x, const float* __restrict__ gamma,
    const float* __restrict__ beta, const float* __restrict__ bp_,
    float* __restrict__ out)
{
    extern __shared__ char smc[];
    float* mu_s = (float*)(smc + OFF_MU);   // [128] per-pair token stats
    float* rs_s = (float*)(smc + OFF_RS);
    int*   grows= (int*)  (smc + OFF_GR);   // [128]
    float* gs   = (float*)(smc + OFF_GS);
    float* bs   = (float*)(smc + OFF_BS);
    float* bps  = (float*)(smc + OFF_BPS);

    const int tid  = threadIdx.x;
    const int lane = tid & 31;
    const int g    = tid >> 8;        // window-group 0/1
    const int tl   = tid & 255;       // tid within group
    const int wid  = tl >> 5;         // warp within group (0..7)

    const uint32_t smc_u = smem_u32(smc);
    const uint32_t buf_u = smc_u + (uint32_t)g * OFF_BUF1;
    const uint32_t wsm_u = smc_u + OFF_WSM;
    const uint32_t as_u  = smc_u + OFF_AS;
    __half2* buf2 = (__half2*)(smc + g * OFF_BUF1);

    if (tid < 256) {
        gs[tid]  = gamma[tid];
        bs[tid]  = beta[tid];
        bps[tid] = bp_[tid];
    }

    // ---- stage FULL Wp (256 rows x 256 halfs) once: 8192 x 16B ----
    {
        const uint4* wsrc = (const uint4*)g_Wh;
#pragma unroll
        for (int i = 0; i < 16; i++) {
            int idx = tid + i * 512;
            int chan = idx >> 5, seg = idx & 31;
            *(uint4*)(smc + OFF_WSM + chan * WSM_SB + seg * 16) = wsrc[idx];
        }
    }

    const int n0 = wid * 32;
    const int r4 = lane >> 2, c4 = lane & 3;
    // ldmatrix lane->address parameters
    const int arow  = (lane & 7) + ((lane >> 3) & 1) * 8;
    const int khi   = (lane >> 4) * 8;
    const int bnrow = ((lane >> 4) & 1) * 8 + (lane & 7);
    const int bkhi  = ((lane >> 3) & 1) * 8;
    const int tkrow = ((lane >> 3) & 1) * 8 + (lane & 7);
    const int tnhi  = (lane >> 4) * 8;

    for (int pair = blockIdx.x; pair < NPAIR; pair += GRID_P) {
        const int w     = pair & 255;
        const int bpair = pair >> 8;
        const int fi    = w >> 2;
        const int nwi   = w & 3;
        const int b     = bpair * 2 + g;

        __syncthreads();   // prev pair fully done (As/grows reusable); Wp/gs visible

        // ---- stage As (64 x 128B): 1 x 16B per thread ----
        {
            int row = tid >> 3, seg = tid & 7;
            *(uint4*)(smc + OFF_AS + row * A_SB + seg * 16) =
                ((const uint4*)(g_Ah + (size_t)w * 4096))[row * 8 + seg];
        }

        // ---- LN pass 1: per-token mean/rstd (4 threads/token, per group) ----
        {
            int tok = tl >> 2, q = tl & 3;
            int tg  = g * 64 + tok;
            int tp  = tok >> 4, wi2 = tok & 15;
            int grow = (b * F_ + fi * TPc + tp) * K_ + nwi * WSZ + wi2;
            if (q == 0) grows[tg] = grow;
            const float4* p = (const float4*)(x + (size_t)grow * EDv + q * 64);
            float s = 0.f, ss = 0.f;
#pragma unroll
            for (int i = 0; i < 16; i++) {
                float4 v = p[i];
                s += v.x + v.y + v.z + v.w;
                ss = fmaf(v.x, v.x, ss); ss = fmaf(v.y, v.y, ss);
                ss = fmaf(v.z, v.z, ss); ss = fmaf(v.w, v.w, ss);
            }
            s  += __shfl_xor_sync(0xffffffffu, s, 1);
            ss += __shfl_xor_sync(0xffffffffu, ss, 1);
            s  += __shfl_xor_sync(0xffffffffu, s, 2);
            ss += __shfl_xor_sync(0xffffffffu, ss, 2);
            if (q == 0) {
                float mu  = s * (1.f / 256.f);
                float var = ss * (1.f / 256.f) - mu * mu;
                mu_s[tg] = mu;
                rs_s[tg] = rsqrtf(var + 1e-5f);
            }
        }
        __syncthreads();   // As + mu/rs/grows visible

        // ---- LN pass 2: normalize (gmem reload, L2-hot) -> half2 into buf ----
        {
            float g0[4], g1[4], e0[4], e1[4];
#pragma unroll
            for (int j = 0; j < 4; j++) {
                int c = 64 * j + 2 * lane;
                g0[j] = gs[c]; g1[j] = gs[c + 1];
                e0[j] = bs[c]; e1[j] = bs[c + 1];
            }
#pragma unroll
            for (int t8 = 0; t8 < 8; t8++) {
                int t = wid * 8 + t8;
                int tg = g * 64 + t;
                float mu = mu_s[tg], rstd = rs_s[tg];
                const float* xr = x + (size_t)grows[tg] * EDv;
#pragma unroll
                for (int j = 0; j < 4; j++) {
                    float2 v = *(const float2*)(xr + 64 * j + 2 * lane);
                    buf2[t * BUF_S32 + 32 * j + lane] = __floats2half2_rn(
                        (v.x - mu) * rstd * g0[j] + e0[j],
                        (v.y - mu) * rstd * g1[j] + e1[j]);
                }
            }
        }
        group_bar(g);   // buf (xn) ready for this group

        // ---- GEMM1: y(64x256) = xn @ Wp^T; full K, no inner barriers ----
        float acc[4][4][4];
#pragma unroll
        for (int mt = 0; mt < 4; mt++)
#pragma unroll
            for (int nt = 0; nt < 4; nt++)
#pragma unroll
                for (int r = 0; r < 4; r++) acc[mt][nt][r] = 0.f;

#pragma unroll
        for (int ks = 0; ks < 16; ks++) {
            uint32_t a[4][4];
            uint32_t abase = buf_u + (uint32_t)arow * BUF_SB +
                             (uint32_t)(ks * 16 + khi) * 2;
#pragma unroll
            for (int mt = 0; mt < 4; mt++)
                LDSM4(a[mt][0], a[mt][1], a[mt][2], a[mt][3],
                      abase + (uint32_t)(mt * 16) * BUF_SB);
            uint32_t bb[4][2];
#pragma unroll
            for (int ntp = 0; ntp < 2; ntp++) {
                uint32_t baddr = wsm_u + (uint32_t)(n0 + ntp * 16 + bnrow) * WSM_SB +
                                 (uint32_t)(ks * 16 + bkhi) * 2;
                LDSM4(bb[2 * ntp][0], bb[2 * ntp][1],
                      bb[2 * ntp + 1][0], bb[2 * ntp + 1][1], baddr);
            }
#pragma unroll
            for (int mt = 0; mt < 4; mt++)
#pragma unroll
                for (int nt = 0; nt < 4; nt++)
                    hmma(acc[mt][nt], a[mt], bb[nt][0], bb[nt][1]);
        }
        group_bar(g);   // group done reading xn -> safe to overwrite buf

        // ---- epilogue1: y = acc + bias -> half2 into buf [tok][chan] ----
        {
            float p0[4], p1[4];
#pragma unroll
            for (int nt = 0; nt < 4; nt++) {
                int c = n0 + nt * 8 + 2 * c4;
                p0[nt] = bps[c]; p1[nt] = bps[c + 1];
            }
#pragma unroll
            for (int mt = 0; mt < 4; mt++)
#pragma unroll
                for (int nt = 0; nt < 4; nt++) {
                    int row = mt * 16 + r4;
                    int cc = (n0 + nt * 8 + 2 * c4) >> 1;
                    buf2[row * BUF_S32 + cc] =
                        __floats2half2_rn(acc[mt][nt][0] + p0[nt], acc[mt][nt][1] + p1[nt]);
                    buf2[(row + 8) * BUF_S32 + cc] =
                        __floats2half2_rn(acc[mt][nt][2] + p0[nt], acc[mt][nt][3] + p1[nt]);
                }
        }
        group_bar(g);   // y visible to whole group

        // ---- GEMM2: z(64x256) = A_w(64x64) @ y ----
#pragma unroll
        for (int mt = 0; mt < 4; mt++)
#pragma unroll
            for (int nt = 0; nt < 4; nt++)
#pragma unroll
                for (int r = 0; r < 4; r++) acc[mt][nt][r] = 0.f;

#pragma unroll
        for (int ks = 0; ks < 4; ks++) {
            uint32_t a[4][4];
            uint32_t abase = as_u + (uint32_t)arow * A_SB + (uint32_t)(ks * 16 + khi) * 2;
#pragma unroll
            for (int mt = 0; mt < 4; mt++)
                LDSM4(a[mt][0], a[mt][1], a[mt][2], a[mt][3],
                      abase + (uint32_t)(mt * 16) * A_SB);
            uint32_t bb[4][2];
#pragma unroll
            for (int ntp = 0; ntp < 2; ntp++) {
                uint32_t baddr = buf_u + (uint32_t)(ks * 16 + tkrow) * BUF_SB +
                                 (uint32_t)(n0 + ntp * 16 + tnhi) * 2;
                LDSM4T(bb[2 * ntp][0], bb[2 * ntp][1],
                       bb[2 * ntp + 1][0], bb[2 * ntp + 1][1], baddr);
            }
#pragma unroll
            for (int mt = 0; mt < 4; mt++)
#pragma unroll
                for (int nt = 0; nt < 4; nt++)
                    hmma(acc[mt][nt], a[mt], bb[nt][0], bb[nt][1]);
        }

        // ---- epilogue2: direct float2 scatter to gmem (window_reverse) ----
#pragma unroll
        for (int mt = 0; mt < 4; mt++) {
            int t0 = mt * 16 + r4;
            float* o0 = out + (size_t)grows[g * 64 + t0] * EDv;
            float* o1 = out + (size_t)grows[g * 64 + t0 + 8] * EDv;
#pragma unroll
            for (int nt = 0; nt < 4; nt++) {
                int col = n0 + nt * 8 + 2 * c4;
                *(float2*)(o0 + col) = make_float2(acc[mt][nt][0], acc[mt][nt][1]);
                *(float2*)(o1 + col) = make_float2(acc[mt][nt][2], acc[mt][nt][3]);
            }
        }
    }
}

// ---------------------------------------------------------------------------
// Launch
// ---------------------------------------------------------------------------
extern "C" void kernel_launch(void* const* d_in, const int* in_sizes, int n_in,
                              void* d_out, int out_size)
{
    const float* x     = (const float*)d_in[0];
    const float* gamma = (const float*)d_in[1];
    const float* beta  = (const float*)d_in[2];
    const float* Wp    = (const float*)d_in[3];
    const float* bp    = (const float*)d_in[4];
    const float* eb    = (const float*)d_in[5];
    const float* deg   = (const float*)d_in[6];
    float* out = (float*)d_out;

    convert_Wp_kernel<<<EDv * EDv / 256, 256>>>(Wp);
    compute_A_kernel<<<WTYPES, 256>>>(deg, eb);

    cudaFuncSetAttribute(fused_persist,
                         cudaFuncAttributeMaxDynamicSharedMemorySize, SMEM_REQ);
    fused_persist<<<GRID_P, 512, SMEM_REQ>>>(x, gamma, beta, bp, out);
}

// round 9
// speedup vs baseline: 1.2085x; 1.2085x over previous
#include <cuda_runtime.h>
#include <cuda_fp16.h>
#include <cstdint>

// Problem constants
#define TPc   4
#define WSZ   16
#define B_    8
#define F_    256
#define K_    64
#define EDv   256
#define NWIN  2048
#define WTYPES 256

// Shared memory layout (byte offsets)
#define OFF_WSM 33792     // buf: 64 rows x 528B (264 halfs)
#define WCH_B   20480     // one Wp chunk buffer: 256 rows x 80B (k=32)
#define OFF_AS  95232     // after 3 chunk buffers
#define OFF_GS  104448
#define OFF_BS  105472
#define OFF_BPS 106496
#define OFF_MU  107520
#define OFF_RS  107776
#define OFF_GR  108032
#define SMEM_REQ 108544

#define BUF_S32 132       // buf row stride in b32 (264 halfs); 528B = 33x16B (odd)
#define BUF_SB  528
#define W_SB    80        // Wp chunk row stride: 32 halfs + 16B pad; 80 = 5x16B (odd)
#define A_SB    144       // As row stride: 64 halfs + 16B pad; 144 = 9x16B (odd)

// Precomputed fp16 operands (device globals: no allocation)
__device__ __half g_Wh[EDv * EDv];            // Wp as fp16, row-major [o][k]
__device__ __half g_Ah[WTYPES * 64 * 64];     // A = deg@eb as fp16

// ---------------------------------------------------------------------------
// Prep kernel 1: Wp -> fp16
// ---------------------------------------------------------------------------
__global__ __launch_bounds__(256) void convert_Wp_kernel(const float* __restrict__ Wp)
{
    int i = blockIdx.x * 256 + threadIdx.x;
    g_Wh[i] = __float2half_rn(Wp[i]);
}

// ---------------------------------------------------------------------------
// Prep kernel 2: A[w] = deg[w] @ eb[w] (fp32 FFMA), stored as fp16
// ---------------------------------------------------------------------------
__global__ __launch_bounds__(256) void compute_A_kernel(
    const float* __restrict__ deg, const float* __restrict__ eb)
{
    __shared__ float Ds[64][64];
    __shared__ float Es[64][68];
    int w = blockIdx.x, tid = threadIdx.x;
    const float* D = deg + (size_t)w * 4096;
    const float* E = eb  + (size_t)w * 4096;
    for (int idx = tid; idx < 4096; idx += 256) {
        Ds[idx >> 6][idx & 63] = D[idx];
        Es[idx >> 6][idx & 63] = E[idx];
    }
    __syncthreads();
    int p  = tid >> 2;
    int q0 = (tid & 3) * 16;
    float acc[16];
#pragma unroll
    for (int j = 0; j < 16; j++) acc[j] = 0.f;
    for (int k = 0; k < 64; k++) {
        float a = Ds[p][k];
#pragma unroll
        for (int j = 0; j < 16; j++) acc[j] = fmaf(a, Es[k][q0 + j], acc[j]);
    }
    __half* Aout = g_Ah + (size_t)w * 4096 + p * 64 + q0;
#pragma unroll
    for (int j = 0; j < 16; j++) Aout[j] = __float2half_rn(acc[j]);
}

// ---------------------------------------------------------------------------
// mma / ldmatrix / cp.async helpers
// ---------------------------------------------------------------------------
__device__ __forceinline__ uint32_t smem_u32(const void* p) {
    uint32_t a;
    asm("{ .reg .u64 t; cvta.to.shared.u64 t, %1; cvt.u32.u64 %0, t; }" : "=r"(a) : "l"(p));
    return a;
}

#define LDSM4(r0, r1, r2, r3, addr) \
    asm volatile("ldmatrix.sync.aligned.m8n8.x4.shared.b16 {%0,%1,%2,%3}, [%4];" \
                 : "=r"(r0), "=r"(r1), "=r"(r2), "=r"(r3) : "r"(addr))
#define LDSM4T(r0, r1, r2, r3, addr) \
    asm volatile("ldmatrix.sync.aligned.m8n8.x4.trans.shared.b16 {%0,%1,%2,%3}, [%4];" \
                 : "=r"(r0), "=r"(r1), "=r"(r2), "=r"(r3) : "r"(addr))

__device__ __forceinline__ void hmma(float c[4], const uint32_t a[4],
                                     uint32_t b0, uint32_t b1) {
    asm volatile(
        "mma.sync.aligned.m16n8k16.row.col.f32.f16.f16.f32 "
        "{%0,%1,%2,%3}, {%4,%5,%6,%7}, {%8,%9}, {%0,%1,%2,%3};"
        : "+f"(c[0]), "+f"(c[1]), "+f"(c[2]), "+f"(c[3])
        : "r"(a[0]), "r"(a[1]), "r"(a[2]), "r"(a[3]), "r"(b0), "r"(b1));
}

#define CP16(dst, src) \
    asm volatile("cp.async.cg.shared.global [%0], [%1], 16;" :: "r"(dst), "l"(src))
#define CP_COMMIT() asm volatile("cp.async.commit_group;" ::: "memory")
#define CP_WAIT1()  asm volatile("cp.async.wait_group 1;" ::: "memory")
#define CP_WAIT0()  asm volatile("cp.async.wait_group 0;" ::: "memory")

// ---------------------------------------------------------------------------
// Fused kernel: one 256-thread CTA per window (2 CTAs/SM). R7 structure with
// 3-stage cp.async Wp pipeline (1 barrier per k=32 chunk, staging off the
// critical path; chunks 0-1 + A tile prefetched under LayerNorm).
// ---------------------------------------------------------------------------
__global__ __launch_bounds__(256, 2) void fused_fp16(
    const float* __restrict__ x, const float* __restrict__ gamma,
    const float* __restrict__ beta, const float* __restrict__ bp_,
    float* __restrict__ out)
{
    extern __shared__ char smc[];
    __half2* buf2 = (__half2*)smc;
    float* gs   = (float*)(smc + OFF_GS);
    float* bs   = (float*)(smc + OFF_BS);
    float* bps  = (float*)(smc + OFF_BPS);
    float* mu_s = (float*)(smc + OFF_MU);
    float* rs_s = (float*)(smc + OFF_RS);
    int*   grows= (int*)  (smc + OFF_GR);

    const uint32_t buf_u = smem_u32(smc);
    const uint32_t wsm_u = buf_u + OFF_WSM;
    const uint32_t as_u  = buf_u + OFF_AS;

    const int tid  = threadIdx.x;
    const int lane = tid & 31;
    const int wid  = tid >> 5;

    const int n   = blockIdx.x;
    const int b   = n >> 8;
    const int w   = n & 255;
    const int fi  = w >> 2;
    const int nwi = w & 3;

    const char* whb = (const char*)g_Wh;      // row = 512B; chunk kc = segs [4kc,4kc+4)
    const char* ahb = (const char*)(g_Ah + (size_t)w * 4096);

    // ---- cp.async prologue: {chunk0 + A tile} group, then {chunk1} group ----
    {
#pragma unroll
        for (int i = 0; i < 4; i++) {
            int idx = tid + i * 256;              // 1024 x 16B
            int chan = idx >> 2, seg = idx & 3;
            CP16(wsm_u + (uint32_t)(chan * W_SB + seg * 16),
                 whb + (size_t)chan * 512 + seg * 16);
        }
#pragma unroll
        for (int i = 0; i < 2; i++) {
            int idx = tid + i * 256;              // 512 x 16B
            int row = idx >> 3, seg = idx & 7;
            CP16(as_u + (uint32_t)(row * A_SB + seg * 16),
                 ahb + (size_t)row * 128 + seg * 16);
        }
        CP_COMMIT();
#pragma unroll
        for (int i = 0; i < 4; i++) {
            int idx = tid + i * 256;
            int chan = idx >> 2, seg = idx & 3;
            CP16(wsm_u + (uint32_t)(WCH_B + chan * W_SB + seg * 16),
                 whb + (size_t)chan * 512 + 64 + seg * 16);
        }
        CP_COMMIT();
    }

    gs[tid]  = gamma[tid];
    bs[tid]  = beta[tid];
    bps[tid] = bp_[tid];

    // ---- LN pass 1: per-token mean/rstd from gmem fp32 (4 threads/token) ----
    {
        int t = tid >> 2, q = tid & 3;
        int tp = t >> 4, wi2 = t & 15;
        int grow = (b * F_ + fi * TPc + tp) * K_ + nwi * WSZ + wi2;
        if (q == 0) grows[t] = grow;
        const float4* p = (const float4*)(x + (size_t)grow * EDv + q * 64);
        float s = 0.f, ss = 0.f;
#pragma unroll
        for (int i = 0; i < 16; i++) {
            float4 v = p[i];
            s += v.x + v.y + v.z + v.w;
            ss = fmaf(v.x, v.x, ss); ss = fmaf(v.y, v.y, ss);
            ss = fmaf(v.z, v.z, ss); ss = fmaf(v.w, v.w, ss);
        }
        s  += __shfl_xor_sync(0xffffffffu, s, 1);
        ss += __shfl_xor_sync(0xffffffffu, ss, 1);
        s  += __shfl_xor_sync(0xffffffffu, s, 2);
        ss += __shfl_xor_sync(0xffffffffu, ss, 2);
        if (q == 0) {
            float mu  = s * (1.f / 256.f);
            float var = ss * (1.f / 256.f) - mu * mu;
            mu_s[t] = mu;
            rs_s[t] = rsqrtf(var + 1e-5f);
        }
    }
    __syncthreads();

    // ---- LN pass 2: normalize (gmem reload, L2-hot) -> half2 into buf ----
    {
        float g0[4], g1[4], e0[4], e1[4];
#pragma unroll
        for (int j = 0; j < 4; j++) {
            int c = 64 * j + 2 * lane;
            g0[j] = gs[c]; g1[j] = gs[c + 1];
            e0[j] = bs[c]; e1[j] = bs[c + 1];
        }
#pragma unroll
        for (int t8 = 0; t8 < 8; t8++) {
            int t = wid * 8 + t8;
            float mu = mu_s[t], rstd = rs_s[t];
            const float* xr = x + (size_t)grows[t] * EDv;
#pragma unroll
            for (int j = 0; j < 4; j++) {
                float2 v = *(const float2*)(xr + 64 * j + 2 * lane);
                buf2[t * BUF_S32 + 32 * j + lane] = __floats2half2_rn(
                    (v.x - mu) * rstd * g0[j] + e0[j],
                    (v.y - mu) * rstd * g1[j] + e1[j]);
            }
        }
    }

    const int n0 = wid * 32;
    const int r4 = lane >> 2, c4 = lane & 3;

    // ldmatrix lane->address parameters
    const int arow  = (lane & 7) + ((lane >> 3) & 1) * 8;  // A row within 16
    const int khi   = (lane >> 4) * 8;                     // +8 halfs (hi-k lanes)
    const int bnrow = ((lane >> 4) & 1) * 8 + (lane & 7);  // B n-row within 16
    const int bkhi  = ((lane >> 3) & 1) * 8;               // B k offset
    const int tkrow = ((lane >> 3) & 1) * 8 + (lane & 7);  // trans: k row within 16
    const int tnhi  = (lane >> 4) * 8;                     // trans: n +8

    float acc[4][4][4];
#pragma unroll
    for (int mt = 0; mt < 4; mt++)
#pragma unroll
        for (int nt = 0; nt < 4; nt++)
#pragma unroll
            for (int r = 0; r < 4; r++) acc[mt][nt][r] = 0.f;

    // ---- GEMM1: y(64x256) = xn @ Wp^T; 8 chunks k=32, 3-stage pipeline ----
    // Per iter: wait(chunk kc) -> bar -> issue chunk kc+2 (buffer (kc+2)%3,
    // overwrites kc-1, consumed before this bar) -> mma chunk kc.
    {
        int bsel = 0;   // buffer of chunk kc: cycles 0,1,2,0,...
        for (int kc = 0; kc < 8; kc++) {
            if (kc == 7) { CP_WAIT0(); } else { CP_WAIT1(); }
            __syncthreads();   // chunk kc visible; all warps done with kc-1 (kc==0: buf/LN)

            if (kc < 6) {
                int kn = kc + 2;
                int nb = bsel - 1; if (nb < 0) nb = 2;   // (kc+2)%3
#pragma unroll
                for (int i = 0; i < 4; i++) {
                    int idx = tid + i * 256;
                    int chan = idx >> 2, seg = idx & 3;
                    CP16(wsm_u + (uint32_t)(nb * WCH_B + chan * W_SB + seg * 16),
                         whb + (size_t)chan * 512 + kn * 64 + seg * 16);
                }
                CP_COMMIT();
            }

#pragma unroll
            for (int ks = 0; ks < 2; ks++) {
                uint32_t a[4][4];
                uint32_t abase = buf_u + (uint32_t)arow * BUF_SB +
                                 (uint32_t)(kc * 32 + ks * 16 + khi) * 2;
#pragma unroll
                for (int mt = 0; mt < 4; mt++)
                    LDSM4(a[mt][0], a[mt][1], a[mt][2], a[mt][3],
                          abase + (uint32_t)(mt * 16) * BUF_SB);
                uint32_t bb[4][2];
#pragma unroll
                for (int ntp = 0; ntp < 2; ntp++) {
                    uint32_t baddr = wsm_u + (uint32_t)bsel * WCH_B +
                                     (uint32_t)(n0 + ntp * 16 + bnrow) * W_SB +
                                     (uint32_t)(ks * 16 + bkhi) * 2;
                    LDSM4(bb[2 * ntp][0], bb[2 * ntp][1],
                          bb[2 * ntp + 1][0], bb[2 * ntp + 1][1], baddr);
                }
#pragma unroll
                for (int mt = 0; mt < 4; mt++)
#pragma unroll
                    for (int nt = 0; nt < 4; nt++)
                        hmma(acc[mt][nt], a[mt], bb[nt][0], bb[nt][1]);
            }
            bsel++; if (bsel == 3) bsel = 0;
        }
    }
    __syncthreads();   // all warps done reading xn -> safe to overwrite buf

    // ---- epilogue1: y = acc + bias -> half2 into buf [tok][chan] ----
    {
        float p0[4], p1[4];
#pragma unroll
        for (int nt = 0; nt < 4; nt++) {
            int c = n0 + nt * 8 + 2 * c4;
            p0[nt] = bps[c]; p1[nt] = bps[c + 1];
        }
#pragma unroll
        for (int mt = 0; mt < 4; mt++)
#pragma unroll
            for (int nt = 0; nt < 4; nt++) {
                int row = mt * 16 + r4;
                int cc = (n0 + nt * 8 + 2 * c4) >> 1;
                buf2[row * BUF_S32 + cc] =
                    __floats2half2_rn(acc[mt][nt][0] + p0[nt], acc[mt][nt][1] + p1[nt]);
                buf2[(row + 8) * BUF_S32 + cc] =
                    __floats2half2_rn(acc[mt][nt][2] + p0[nt], acc[mt][nt][3] + p1[nt]);
            }
    }
    __syncthreads();

    // ---- GEMM2: z(64x256) = A_w(64x64) @ y ----
#pragma unroll
    for (int mt = 0; mt < 4; mt++)
#pragma unroll
        for (int nt = 0; nt < 4; nt++)
#pragma unroll
            for (int r = 0; r < 4; r++) acc[mt][nt][r] = 0.f;

#pragma unroll
    for (int ks = 0; ks < 4; ks++) {
        uint32_t a[4][4];
        uint32_t abase = as_u + (uint32_t)arow * A_SB + (uint32_t)(ks * 16 + khi) * 2;
#pragma unroll
        for (int mt = 0; mt < 4; mt++)
            LDSM4(a[mt][0], a[mt][1], a[mt][2], a[mt][3],
                  abase + (uint32_t)(mt * 16) * A_SB);
        uint32_t bb[4][2];
#pragma unroll
        for (int ntp = 0; ntp < 2; ntp++) {
            uint32_t baddr = buf_u + (uint32_t)(ks * 16 + tkrow) * BUF_SB +
                             (uint32_t)(n0 + ntp * 16 + tnhi) * 2;
            LDSM4T(bb[2 * ntp][0], bb[2 * ntp][1],
                   bb[2 * ntp + 1][0], bb[2 * ntp + 1][1], baddr);
        }
#pragma unroll
        for (int mt = 0; mt < 4; mt++)
#pragma unroll
            for (int nt = 0; nt < 4; nt++)
                hmma(acc[mt][nt], a[mt], bb[nt][0], bb[nt][1]);
    }

    // ---- epilogue2: direct float2 scatter to gmem (window_reverse) ----
#pragma unroll
    for (int mt = 0; mt < 4; mt++) {
        int t0 = mt * 16 + r4;
        float* o0 = out + (size_t)grows[t0] * EDv;
        float* o1 = out + (size_t)grows[t0 + 8] * EDv;
#pragma unroll
        for (int nt = 0; nt < 4; nt++) {
            int col = n0 + nt * 8 + 2 * c4;
            *(float2*)(o0 + col) = make_float2(acc[mt][nt][0], acc[mt][nt][1]);
            *(float2*)(o1 + col) = make_float2(acc[mt][nt][2], acc[mt][nt][3]);
        }
    }
}

// ---------------------------------------------------------------------------
// Launch
// ---------------------------------------------------------------------------
extern "C" void kernel_launch(void* const* d_in, const int* in_sizes, int n_in,
                              void* d_out, int out_size)
{
    const float* x     = (const float*)d_in[0];
    const float* gamma = (const float*)d_in[1];
    const float* beta  = (const float*)d_in[2];
    const float* Wp    = (const float*)d_in[3];
    const float* bp    = (const float*)d_in[4];
    const float* eb    = (const float*)d_in[5];
    const float* deg   = (const float*)d_in[6];
    float* out = (float*)d_out;

    convert_Wp_kernel<<<EDv * EDv / 256, 256>>>(Wp);
    compute_A_kernel<<<WTYPES, 256>>>(deg, eb);

    cudaFuncSetAttribute(fused_fp16,
                         cudaFuncAttributeMaxDynamicSharedMemorySize, SMEM_REQ);
    fused_fp16<<<NWIN, 256, SMEM_REQ>>>(x, gamma, beta, bp, out);
}

// round 10
// speedup vs baseline: 1.4964x; 1.2382x over previous
#include <cuda_runtime.h>
#include <cuda_fp16.h>
#include <cstdint>

// Problem constants
#define TPc   4
#define WSZ   16
#define B_    8
#define F_    256
#define K_    64
#define EDv   256
#define NWIN  2048
#define WTYPES 256

// Shared memory layout (byte offsets)
#define OFF_WSM 33792     // buf: 64 rows x 528B (264 halfs)
#define WCH_B   20480     // one Wp chunk buffer: 256 rows x 80B (k=32)
#define OFF_AS  95232     // after 3 chunk buffers
#define OFF_GS  104448
#define OFF_BS  105472
#define OFF_BPS 106496
#define SMEM_REQ 107520

#define BUF_S32 132       // buf row stride in b32 (264 halfs); 528B = 33x16B (odd)
#define BUF_SB  528
#define W_SB    80        // Wp chunk row stride: 32 halfs + 16B pad; 80 = 5x16B (odd)
#define A_SB    144       // As row stride: 64 halfs + 16B pad; 144 = 9x16B (odd)

// Precomputed fp16 operands (device globals: no allocation)
__device__ __half g_Wh[EDv * EDv];            // Wp as fp16, row-major [o][k]
__device__ __half g_Ah[WTYPES * 64 * 64];     // A = deg@eb as fp16

// ---------------------------------------------------------------------------
// Prep kernel (merged): blocks [0,256) compute A[w] = deg@eb (fp32 FFMA) -> fp16
//                       blocks [256,320) convert Wp -> fp16
// ---------------------------------------------------------------------------
__global__ __launch_bounds__(256) void prep_kernel(
    const float* __restrict__ deg, const float* __restrict__ eb,
    const float* __restrict__ Wp)
{
    __shared__ float Ds[64][64];
    __shared__ float Es[64][68];
    int tid = threadIdx.x;

    if (blockIdx.x >= WTYPES) {
        // convert Wp: 64 blocks x 256 threads x 4 floats
        int i = (blockIdx.x - WTYPES) * 256 + tid;      // float4 index
        float4 v = ((const float4*)Wp)[i];
        __half2* dst = (__half2*)g_Wh;
        dst[2 * i]     = __floats2half2_rn(v.x, v.y);
        dst[2 * i + 1] = __floats2half2_rn(v.z, v.w);
        return;
    }

    int w = blockIdx.x;
    const float* D = deg + (size_t)w * 4096;
    const float* E = eb  + (size_t)w * 4096;
    for (int idx = tid; idx < 4096; idx += 256) {
        Ds[idx >> 6][idx & 63] = D[idx];
        Es[idx >> 6][idx & 63] = E[idx];
    }
    __syncthreads();
    int p  = tid >> 2;
    int q0 = (tid & 3) * 16;
    float acc[16];
#pragma unroll
    for (int j = 0; j < 16; j++) acc[j] = 0.f;
    for (int k = 0; k < 64; k++) {
        float a = Ds[p][k];
#pragma unroll
        for (int j = 0; j < 16; j++) acc[j] = fmaf(a, Es[k][q0 + j], acc[j]);
    }
    __half* Aout = g_Ah + (size_t)w * 4096 + p * 64 + q0;
#pragma unroll
    for (int j = 0; j < 16; j++) Aout[j] = __float2half_rn(acc[j]);
}

// ---------------------------------------------------------------------------
// mma / ldmatrix / cp.async helpers
// ---------------------------------------------------------------------------
__device__ __forceinline__ uint32_t smem_u32(const void* p) {
    uint32_t a;
    asm("{ .reg .u64 t; cvta.to.shared.u64 t, %1; cvt.u32.u64 %0, t; }" : "=r"(a) : "l"(p));
    return a;
}

#define LDSM4(r0, r1, r2, r3, addr) \
    asm volatile("ldmatrix.sync.aligned.m8n8.x4.shared.b16 {%0,%1,%2,%3}, [%4];" \
                 : "=r"(r0), "=r"(r1), "=r"(r2), "=r"(r3) : "r"(addr))
#define LDSM4T(r0, r1, r2, r3, addr) \
    asm volatile("ldmatrix.sync.aligned.m8n8.x4.trans.shared.b16 {%0,%1,%2,%3}, [%4];" \
                 : "=r"(r0), "=r"(r1), "=r"(r2), "=r"(r3) : "r"(addr))

__device__ __forceinline__ void hmma(float c[4], const uint32_t a[4],
                                     uint32_t b0, uint32_t b1) {
    asm volatile(
        "mma.sync.aligned.m16n8k16.row.col.f32.f16.f16.f32 "
        "{%0,%1,%2,%3}, {%4,%5,%6,%7}, {%8,%9}, {%0,%1,%2,%3};"
        : "+f"(c[0]), "+f"(c[1]), "+f"(c[2]), "+f"(c[3])
        : "r"(a[0]), "r"(a[1]), "r"(a[2]), "r"(a[3]), "r"(b0), "r"(b1));
}

#define CP16(dst, src) \
    asm volatile("cp.async.cg.shared.global [%0], [%1], 16;" :: "r"(dst), "l"(src))
#define CP_COMMIT() asm volatile("cp.async.commit_group;" ::: "memory")
#define CP_WAIT1()  asm volatile("cp.async.wait_group 1;" ::: "memory")
#define CP_WAIT0()  asm volatile("cp.async.wait_group 0;" ::: "memory")

// ---------------------------------------------------------------------------
// Fused kernel: one 256-thread CTA per window (2 CTAs/SM).
//   cp.async prologue (Wp0+A, Wp1) -> single-pass register LN -> buf(half)
//   -> GEMM1 (8 chunks k=32, 3-stage cp.async pipeline, 1 bar/chunk)
//   -> y in buf -> GEMM2 (A_w @ y) -> direct float2 scatter (window_reverse)
// ---------------------------------------------------------------------------
__global__ __launch_bounds__(256, 2) void fused_fp16(
    const float* __restrict__ x, const float* __restrict__ gamma,
    const float* __restrict__ beta, const float* __restrict__ bp_,
    float* __restrict__ out)
{
    extern __shared__ char smc[];
    __half2* buf2 = (__half2*)smc;
    float* gs   = (float*)(smc + OFF_GS);
    float* bs   = (float*)(smc + OFF_BS);
    float* bps  = (float*)(smc + OFF_BPS);

    const uint32_t buf_u = smem_u32(smc);
    const uint32_t wsm_u = buf_u + OFF_WSM;
    const uint32_t as_u  = buf_u + OFF_AS;

    const int tid  = threadIdx.x;
    const int lane = tid & 31;
    const int wid  = tid >> 5;

    const int n   = blockIdx.x;
    const int b   = n >> 8;
    const int w   = n & 255;
    const int fi  = w >> 2;
    const int nwi = w & 3;
    // base row index in (B*F*K) space for this window; token t -> gbase + (t>>4)*K_ + (t&15)
    const int gbase = (b * F_ + fi * TPc) * K_ + nwi * WSZ;

    const char* whb = (const char*)g_Wh;      // row = 512B; chunk kc = segs [4kc,4kc+4)
    const char* ahb = (const char*)(g_Ah + (size_t)w * 4096);

    // ---- cp.async prologue: {chunk0 + A tile} group, then {chunk1} group ----
    {
#pragma unroll
        for (int i = 0; i < 4; i++) {
            int idx = tid + i * 256;              // 1024 x 16B
            int chan = idx >> 2, seg = idx & 3;
            CP16(wsm_u + (uint32_t)(chan * W_SB + seg * 16),
                 whb + (size_t)chan * 512 + seg * 16);
        }
#pragma unroll
        for (int i = 0; i < 2; i++) {
            int idx = tid + i * 256;              // 512 x 16B
            int row = idx >> 3, seg = idx & 7;
            CP16(as_u + (uint32_t)(row * A_SB + seg * 16),
                 ahb + (size_t)row * 128 + seg * 16);
        }
        CP_COMMIT();
#pragma unroll
        for (int i = 0; i < 4; i++) {
            int idx = tid + i * 256;
            int chan = idx >> 2, seg = idx & 3;
            CP16(wsm_u + (uint32_t)(WCH_B + chan * W_SB + seg * 16),
                 whb + (size_t)chan * 512 + 64 + seg * 16);
        }
        CP_COMMIT();
    }

    gs[tid]  = gamma[tid];
    bs[tid]  = beta[tid];
    bps[tid] = bp_[tid];
    __syncthreads();   // gs/bs visible (LN reads other threads' entries)

    // ---- single-pass LayerNorm: warp owns tokens wid*8..wid*8+7 ----
    // lane holds cols {64j+2*lane, 64j+2*lane+1} of each token (8 floats/token)
    {
        float xv[8][8];
#pragma unroll
        for (int t8 = 0; t8 < 8; t8++) {
            int t = wid * 8 + t8;
            const float* xr = x + (size_t)(gbase + (t >> 4) * K_ + (t & 15)) * EDv;
#pragma unroll
            for (int j = 0; j < 4; j++) {
                float2 v = *(const float2*)(xr + 64 * j + 2 * lane);
                xv[t8][2 * j]     = v.x;
                xv[t8][2 * j + 1] = v.y;
            }
        }
        float g0[4], g1[4], e0[4], e1[4];
#pragma unroll
        for (int j = 0; j < 4; j++) {
            int c = 64 * j + 2 * lane;
            g0[j] = gs[c]; g1[j] = gs[c + 1];
            e0[j] = bs[c]; e1[j] = bs[c + 1];
        }
#pragma unroll
        for (int t8 = 0; t8 < 8; t8++) {
            float s = 0.f, ss = 0.f;
#pragma unroll
            for (int i = 0; i < 8; i++) {
                float v = xv[t8][i];
                s += v; ss = fmaf(v, v, ss);
            }
#pragma unroll
            for (int off = 16; off >= 1; off >>= 1) {
                s  += __shfl_xor_sync(0xffffffffu, s, off);
                ss += __shfl_xor_sync(0xffffffffu, ss, off);
            }
            float mu   = s * (1.f / 256.f);
            float var  = ss * (1.f / 256.f) - mu * mu;
            float rstd = rsqrtf(var + 1e-5f);
            int t = wid * 8 + t8;
#pragma unroll
            for (int j = 0; j < 4; j++) {
                buf2[t * BUF_S32 + 32 * j + lane] = __floats2half2_rn(
                    (xv[t8][2 * j]     - mu) * rstd * g0[j] + e0[j],
                    (xv[t8][2 * j + 1] - mu) * rstd * g1[j] + e1[j]);
            }
        }
    }

    const int n0 = wid * 32;
    const int r4 = lane >> 2, c4 = lane & 3;

    // ldmatrix lane->address parameters
    const int arow  = (lane & 7) + ((lane >> 3) & 1) * 8;  // A row within 16
    const int khi   = (lane >> 4) * 8;                     // +8 halfs (hi-k lanes)
    const int bnrow = ((lane >> 4) & 1) * 8 + (lane & 7);  // B n-row within 16
    const int bkhi  = ((lane >> 3) & 1) * 8;               // B k offset
    const int tkrow = ((lane >> 3) & 1) * 8 + (lane & 7);  // trans: k row within 16
    const int tnhi  = (lane >> 4) * 8;                     // trans: n +8

    float acc[4][4][4];
#pragma unroll
    for (int mt = 0; mt < 4; mt++)
#pragma unroll
        for (int nt = 0; nt < 4; nt++)
#pragma unroll
            for (int r = 0; r < 4; r++) acc[mt][nt][r] = 0.f;

    // ---- GEMM1: y(64x256) = xn @ Wp^T; 8 chunks k=32, 3-stage pipeline ----
    {
        int bsel = 0;   // buffer of chunk kc: cycles 0,1,2,0,...
        for (int kc = 0; kc < 8; kc++) {
            if (kc == 7) { CP_WAIT0(); } else { CP_WAIT1(); }
            __syncthreads();   // chunk kc visible; kc==0: also LN buf stores visible

            if (kc < 6) {
                int kn = kc + 2;
                int nb = bsel - 1; if (nb < 0) nb = 2;   // (kc+2)%3
#pragma unroll
                for (int i = 0; i < 4; i++) {
                    int idx = tid + i * 256;
                    int chan = idx >> 2, seg = idx & 3;
                    CP16(wsm_u + (uint32_t)(nb * WCH_B + chan * W_SB + seg * 16),
                         whb + (size_t)chan * 512 + kn * 64 + seg * 16);
                }
                CP_COMMIT();
            }

#pragma unroll
            for (int ks = 0; ks < 2; ks++) {
                uint32_t a[4][4];
                uint32_t abase = buf_u + (uint32_t)arow * BUF_SB +
                                 (uint32_t)(kc * 32 + ks * 16 + khi) * 2;
#pragma unroll
                for (int mt = 0; mt < 4; mt++)
                    LDSM4(a[mt][0], a[mt][1], a[mt][2], a[mt][3],
                          abase + (uint32_t)(mt * 16) * BUF_SB);
                uint32_t bb[4][2];
#pragma unroll
                for (int ntp = 0; ntp < 2; ntp++) {
                    uint32_t baddr = wsm_u + (uint32_t)bsel * WCH_B +
                                     (uint32_t)(n0 + ntp * 16 + bnrow) * W_SB +
                                     (uint32_t)(ks * 16 + bkhi) * 2;
                    LDSM4(bb[2 * ntp][0], bb[2 * ntp][1],
                          bb[2 * ntp + 1][0], bb[2 * ntp + 1][1], baddr);
                }
#pragma unroll
                for (int mt = 0; mt < 4; mt++)
#pragma unroll
                    for (int nt = 0; nt < 4; nt++)
                        hmma(acc[mt][nt], a[mt], bb[nt][0], bb[nt][1]);
            }
            bsel++; if (bsel == 3) bsel = 0;
        }
    }
    __syncthreads();   // all warps done reading xn -> safe to overwrite buf

    // ---- epilogue1: y = acc + bias -> half2 into buf [tok][chan] ----
    {
        float p0[4], p1[4];
#pragma unroll
        for (int nt = 0; nt < 4; nt++) {
            int c = n0 + nt * 8 + 2 * c4;
            p0[nt] = bps[c]; p1[nt] = bps[c + 1];
        }
#pragma unroll
        for (int mt = 0; mt < 4; mt++)
#pragma unroll
            for (int nt = 0; nt < 4; nt++) {
                int row = mt * 16 + r4;
                int cc = (n0 + nt * 8 + 2 * c4) >> 1;
                buf2[row * BUF_S32 + cc] =
                    __floats2half2_rn(acc[mt][nt][0] + p0[nt], acc[mt][nt][1] + p1[nt]);
                buf2[(row + 8) * BUF_S32 + cc] =
                    __floats2half2_rn(acc[mt][nt][2] + p0[nt], acc[mt][nt][3] + p1[nt]);
            }
    }
    __syncthreads();

    // ---- GEMM2: z(64x256) = A_w(64x64) @ y ----
#pragma unroll
    for (int mt = 0; mt < 4; mt++)
#pragma unroll
        for (int nt = 0; nt < 4; nt++)
#pragma unroll
            for (int r = 0; r < 4; r++) acc[mt][nt][r] = 0.f;

#pragma unroll
    for (int ks = 0; ks < 4; ks++) {
        uint32_t a[4][4];
        uint32_t abase = as_u + (uint32_t)arow * A_SB + (uint32_t)(ks * 16 + khi) * 2;
#pragma unroll
        for (int mt = 0; mt < 4; mt++)
            LDSM4(a[mt][0], a[mt][1], a[mt][2], a[mt][3],
                  abase + (uint32_t)(mt * 16) * A_SB);
        uint32_t bb[4][2];
#pragma unroll
        for (int ntp = 0; ntp < 2; ntp++) {
            uint32_t baddr = buf_u + (uint32_t)(ks * 16 + tkrow) * BUF_SB +
                             (uint32_t)(n0 + ntp * 16 + tnhi) * 2;
            LDSM4T(bb[2 * ntp][0], bb[2 * ntp][1],
                   bb[2 * ntp + 1][0], bb[2 * ntp + 1][1], baddr);
        }
#pragma unroll
        for (int mt = 0; mt < 4; mt++)
#pragma unroll
            for (int nt = 0; nt < 4; nt++)
                hmma(acc[mt][nt], a[mt], bb[nt][0], bb[nt][1]);
    }

    // ---- epilogue2: direct float2 scatter to gmem (window_reverse) ----
#pragma unroll
    for (int mt = 0; mt < 4; mt++) {
        int t0 = mt * 16 + r4;
        int t1 = t0 + 8;
        float* o0 = out + (size_t)(gbase + (t0 >> 4) * K_ + (t0 & 15)) * EDv;
        float* o1 = out + (size_t)(gbase + (t1 >> 4) * K_ + (t1 & 15)) * EDv;
#pragma unroll
        for (int nt = 0; nt < 4; nt++) {
            int col = n0 + nt * 8 + 2 * c4;
            *(float2*)(o0 + col) = make_float2(acc[mt][nt][0], acc[mt][nt][1]);
            *(float2*)(o1 + col) = make_float2(acc[mt][nt][2], acc[mt][nt][3]);
        }
    }
}

// ---------------------------------------------------------------------------
// Launch
// ---------------------------------------------------------------------------
extern "C" void kernel_launch(void* const* d_in, const int* in_sizes, int n_in,
                              void* d_out, int out_size)
{
    const float* x     = (const float*)d_in[0];
    const float* gamma = (const float*)d_in[1];
    const float* beta  = (const float*)d_in[2];
    const float* Wp    = (const float*)d_in[3];
    const float* bp    = (const float*)d_in[4];
    const float* eb    = (const float*)d_in[5];
    const float* deg   = (const float*)d_in[6];
    float* out = (float*)d_out;

    prep_kernel<<<WTYPES + 64, 256>>>(deg, eb, Wp);

    cudaFuncSetAttribute(fused_fp16,
                         cudaFuncAttributeMaxDynamicSharedMemorySize, SMEM_REQ);
    fused_fp16<<<NWIN, 256, SMEM_REQ>>>(x, gamma, beta, bp, out);
}

// round 13
// speedup vs baseline: 1.5362x; 1.0266x over previous
#include <cuda_runtime.h>
#include <cuda_fp16.h>
#include <cstdint>
#include <cstring>

// Problem constants
#define TPc   4
#define WSZ   16
#define B_    8
#define F_    256
#define K_    64
#define EDv   256
#define NWIN  2048
#define WTYPES 256

// Shared memory layout (byte offsets)
#define OFF_WSM 33792     // buf: 64 rows x 528B (264 halfs)
#define WCH_B   20480     // one Wp chunk buffer: 256 rows x 80B (k=32)
#define OFF_AS  95232     // after 3 chunk buffers
#define SMEM_REQ 104448

#define BUF_S32 132       // buf row stride in b32 (264 halfs); 528B = 33x16B (odd)
#define BUF_SB  528
#define W_SB    80        // Wp chunk row stride: 32 halfs + 16B pad; 80 = 5x16B (odd)
#define A_SB    144       // As row stride: 64 halfs + 16B pad; 144 = 9x16B (odd)

// Precomputed fp16 operands (device globals: no allocation)
__device__ __half g_Wh[EDv * EDv];            // Wp as fp16, row-major [o][k]
__device__ __half g_Ah[WTYPES * 64 * 64];     // A = deg@eb as fp16

// ---------------------------------------------------------------------------
// Prep kernel: blocks [0,512) compute half of A[w] = deg@eb (fp32) -> fp16
//              blocks [512,576) convert Wp -> fp16
// ---------------------------------------------------------------------------
__global__ __launch_bounds__(256) void prep_kernel(
    const float* __restrict__ deg, const float* __restrict__ eb,
    const float* __restrict__ Wp)
{
    __shared__ float Ds[32][64];
    __shared__ float Es[64][68];
    int tid = threadIdx.x;

    if (blockIdx.x >= 2 * WTYPES) {
        // convert Wp: 64 blocks x 256 threads x 4 floats
        int i = (blockIdx.x - 2 * WTYPES) * 256 + tid;   // float4 index
        float4 v = ((const float4*)Wp)[i];
        __half2* dst = (__half2*)g_Wh;
        dst[2 * i]     = __floats2half2_rn(v.x, v.y);
        dst[2 * i + 1] = __floats2half2_rn(v.z, v.w);
        return;
    }

    int w    = blockIdx.x >> 1;
    int half = blockIdx.x & 1;
    const float* D = deg + (size_t)w * 4096 + half * 32 * 64;
    const float* E = eb  + (size_t)w * 4096;
    for (int idx = tid; idx < 2048; idx += 256)
        Ds[idx >> 6][idx & 63] = D[idx];
    for (int idx = tid; idx < 4096; idx += 256)
        Es[idx >> 6][idx & 63] = E[idx];
    __syncthreads();
    int pr = tid >> 3;                 // local row 0..31
    int q0 = (tid & 7) * 8;
    float acc[8];
#pragma unroll
    for (int j = 0; j < 8; j++) acc[j] = 0.f;
    for (int k = 0; k < 64; k++) {
        float a = Ds[pr][k];
#pragma unroll
        for (int j = 0; j < 8; j++) acc[j] = fmaf(a, Es[k][q0 + j], acc[j]);
    }
    __half* Aout = g_Ah + (size_t)w * 4096 + (half * 32 + pr) * 64 + q0;
#pragma unroll
    for (int j = 0; j < 8; j++) Aout[j] = __float2half_rn(acc[j]);
}

// ---------------------------------------------------------------------------
// mma / ldmatrix / stmatrix / cp.async helpers
// ---------------------------------------------------------------------------
__device__ __forceinline__ uint32_t smem_u32(const void* p) {
    uint32_t a;
    asm("{ .reg .u64 t; cvta.to.shared.u64 t, %1; cvt.u32.u64 %0, t; }" : "=r"(a) : "l"(p));
    return a;
}

#define LDSM4(r0, r1, r2, r3, addr) \
    asm volatile("ldmatrix.sync.aligned.m8n8.x4.shared.b16 {%0,%1,%2,%3}, [%4];" \
                 : "=r"(r0), "=r"(r1), "=r"(r2), "=r"(r3) : "r"(addr))
#define LDSM4T(r0, r1, r2, r3, addr) \
    asm volatile("ldmatrix.sync.aligned.m8n8.x4.trans.shared.b16 {%0,%1,%2,%3}, [%4];" \
                 : "=r"(r0), "=r"(r1), "=r"(r2), "=r"(r3) : "r"(addr))
#define STSM4(addr, r0, r1, r2, r3) \
    asm volatile("stmatrix.sync.aligned.m8n8.x4.shared.b16 [%0], {%1,%2,%3,%4};" \
                 :: "r"(addr), "r"(r0), "r"(r1), "r"(r2), "r"(r3) : "memory")

__device__ __forceinline__ void hmma(float c[4], const uint32_t a[4],
                                     uint32_t b0, uint32_t b1) {
    asm volatile(
        "mma.sync.aligned.m16n8k16.row.col.f32.f16.f16.f32 "
        "{%0,%1,%2,%3}, {%4,%5,%6,%7}, {%8,%9}, {%0,%1,%2,%3};"
        : "+f"(c[0]), "+f"(c[1]), "+f"(c[2]), "+f"(c[3])
        : "r"(a[0]), "r"(a[1]), "r"(a[2]), "r"(a[3]), "r"(b0), "r"(b1));
}

#define CP16(dst, src) \
    asm volatile("cp.async.cg.shared.global [%0], [%1], 16;" :: "r"(dst), "l"(src))
#define CP_COMMIT() asm volatile("cp.async.commit_group;" ::: "memory")
#define CP_WAIT1()  asm volatile("cp.async.wait_group 1;" ::: "memory")
#define CP_WAIT0()  asm volatile("cp.async.wait_group 0;" ::: "memory")

__device__ __forceinline__ uint32_t h2u(float a, float b) {
    __half2 h = __floats2half2_rn(a, b);
    uint32_t u;
    memcpy(&u, &h, 4);
    return u;
}

// ---------------------------------------------------------------------------
// Fused kernel: one 256-thread CTA per window (2 CTAs/SM).
// Only TWO CTA barriers total (post-LN, post-GEMM1):
//   GEMM1 staging is warp-private (cp.async + per-thread wait + syncwarp),
//   epilogue1 -> GEMM2 is warp-local (stmatrix then own-col ldmatrix),
//   params loaded straight from gmem (no smem, no bar).
// ---------------------------------------------------------------------------
__global__ __launch_bounds__(256, 2) void fused_fp16(
    const float* __restrict__ x, const float* __restrict__ gamma,
    const float* __restrict__ beta, const float* __restrict__ bp_,
    float* __restrict__ out)
{
    extern __shared__ char smc[];
    const uint32_t buf_u = smem_u32(smc);
    const uint32_t wsm_u = buf_u + OFF_WSM;
    const uint32_t as_u  = buf_u + OFF_AS;

    const int tid  = threadIdx.x;
    const int lane = tid & 31;
    const int wid  = tid >> 5;
    const int n0   = wid * 32;

    const int n   = blockIdx.x;
    const int b   = n >> 8;
    const int w   = n & 255;
    const int fi  = w >> 2;
    const int nwi = w & 3;
    const int gbase = (b * F_ + fi * TPc) * K_ + nwi * WSZ;

    const char* whb = (const char*)g_Wh;      // row = 512B
    const char* ahb = (const char*)(g_Ah + (size_t)w * 4096);

    // ---- prologue: warp-private chunk0 (+A coop) -> G0, chunk1 -> G1 ----
    {
        int r0 = n0 + (lane >> 2), sg = lane & 3;
#pragma unroll
        for (int i = 0; i < 4; i++) {
            int row = r0 + 8 * i;
            CP16(wsm_u + (uint32_t)(row * W_SB + sg * 16),
                 whb + (size_t)row * 512 + sg * 16);
        }
#pragma unroll
        for (int i = 0; i < 2; i++) {
            int idx = tid + i * 256;          // A tile: 512 x 16B cooperative
            int row = idx >> 3, seg = idx & 7;
            CP16(as_u + (uint32_t)(row * A_SB + seg * 16),
                 ahb + (size_t)row * 128 + seg * 16);
        }
        CP_COMMIT();
#pragma unroll
        for (int i = 0; i < 4; i++) {
            int row = r0 + 8 * i;
            CP16(wsm_u + (uint32_t)(WCH_B + row * W_SB + sg * 16),
                 whb + (size_t)row * 512 + 64 + sg * 16);
        }
        CP_COMMIT();
    }

    // ---- single-pass LayerNorm: warp owns tokens wid*8..+7; params from gmem ----
    // lane holds cols {128j + 4*lane .. +3}, j=0,1
    {
        float gg[2][4], ee[2][4];
#pragma unroll
        for (int j = 0; j < 2; j++) {
            float4 G = *(const float4*)(gamma + 128 * j + 4 * lane);
            float4 E = *(const float4*)(beta  + 128 * j + 4 * lane);
            gg[j][0] = G.x; gg[j][1] = G.y; gg[j][2] = G.z; gg[j][3] = G.w;
            ee[j][0] = E.x; ee[j][1] = E.y; ee[j][2] = E.z; ee[j][3] = E.w;
        }
        float xv[8][2][4];
#pragma unroll
        for (int t8 = 0; t8 < 8; t8++) {
            int t = wid * 8 + t8;
            const float* xr = x + (size_t)(gbase + (t >> 4) * K_ + (t & 15)) * EDv;
#pragma unroll
            for (int j = 0; j < 2; j++) {
                float4 v = *(const float4*)(xr + 128 * j + 4 * lane);
                xv[t8][j][0] = v.x; xv[t8][j][1] = v.y;
                xv[t8][j][2] = v.z; xv[t8][j][3] = v.w;
            }
        }
#pragma unroll
        for (int t8 = 0; t8 < 8; t8++) {
            float s = 0.f, ss = 0.f;
#pragma unroll
            for (int j = 0; j < 2; j++)
#pragma unroll
                for (int i = 0; i < 4; i++) {
                    float v = xv[t8][j][i];
                    s += v; ss = fmaf(v, v, ss);
                }
#pragma unroll
            for (int off = 16; off >= 1; off >>= 1) {
                s  += __shfl_xor_sync(0xffffffffu, s, off);
                ss += __shfl_xor_sync(0xffffffffu, ss, off);
            }
            float mu   = s * (1.f / 256.f);
            float var  = ss * (1.f / 256.f) - mu * mu;
            float rstd = rsqrtf(var + 1e-5f);
            int t = wid * 8 + t8;
#pragma unroll
            for (int j = 0; j < 2; j++) {
                uint2 st;
                st.x = h2u((xv[t8][j][0] - mu) * rstd * gg[j][0] + ee[j][0],
                           (xv[t8][j][1] - mu) * rstd * gg[j][1] + ee[j][1]);
                st.y = h2u((xv[t8][j][2] - mu) * rstd * gg[j][2] + ee[j][2],
                           (xv[t8][j][3] - mu) * rstd * gg[j][3] + ee[j][3]);
                *(uint2*)(smc + t * BUF_SB + 256 * j + 8 * lane) = st;
            }
        }
    }
    __syncthreads();   // BAR 1: xn visible to all warps

    const int r4 = lane >> 2, c4 = lane & 3;
    // ldmatrix lane->address parameters
    const int arow  = (lane & 7) + ((lane >> 3) & 1) * 8;  // A row within 16
    const int khi   = (lane >> 4) * 8;                     // +8 halfs (hi-k lanes)
    const int bnrow = ((lane >> 4) & 1) * 8 + (lane & 7);  // B n-row within 16
    const int bkhi  = ((lane >> 3) & 1) * 8;               // B k offset
    const int tkrow = ((lane >> 3) & 1) * 8 + (lane & 7);  // trans: k row within 16
    const int tnhi  = (lane >> 4) * 8;                     // trans: n +8

    float acc[4][4][4];
#pragma unroll
    for (int mt = 0; mt < 4; mt++)
#pragma unroll
        for (int nt = 0; nt < 4; nt++)
#pragma unroll
            for (int r = 0; r < 4; r++) acc[mt][nt][r] = 0.f;

    // ---- GEMM1: y(64x256) = xn @ Wp^T; 8 chunks k=32, warp-autonomous ----
    {
        const int r0 = n0 + (lane >> 2), sg = lane & 3;
        int bsel = 0;
        for (int kc = 0; kc < 8; kc++) {
            if (kc == 7) { CP_WAIT0(); } else { CP_WAIT1(); }
            __syncwarp();      // own chunk kc visible warp-wide

            if (kc < 6) {
                int kn = kc + 2;
                int nb = bsel - 1; if (nb < 0) nb = 2;   // (kc+2)%3
#pragma unroll
                for (int i = 0; i < 4; i++) {
                    int row = r0 + 8 * i;
                    CP16(wsm_u + (uint32_t)(nb * WCH_B + row * W_SB + sg * 16),
                         whb + (size_t)row * 512 + kn * 64 + sg * 16);
                }
                CP_COMMIT();
            }

#pragma unroll
            for (int ks = 0; ks < 2; ks++) {
                uint32_t a[4][4];
                uint32_t abase = buf_u + (uint32_t)arow * BUF_SB +
                                 (uint32_t)(kc * 32 + ks * 16 + khi) * 2;
#pragma unroll
                for (int mt = 0; mt < 4; mt++)
                    LDSM4(a[mt][0], a[mt][1], a[mt][2], a[mt][3],
                          abase + (uint32_t)(mt * 16) * BUF_SB);
                uint32_t bb[4][2];
#pragma unroll
                for (int ntp = 0; ntp < 2; ntp++) {
                    uint32_t baddr = wsm_u + (uint32_t)bsel * WCH_B +
                                     (uint32_t)(n0 + ntp * 16 + bnrow) * W_SB +
                                     (uint32_t)(ks * 16 + bkhi) * 2;
                    LDSM4(bb[2 * ntp][0], bb[2 * ntp][1],
                          bb[2 * ntp + 1][0], bb[2 * ntp + 1][1], baddr);
                }
#pragma unroll
                for (int mt = 0; mt < 4; mt++)
#pragma unroll
                    for (int nt = 0; nt < 4; nt++)
                        hmma(acc[mt][nt], a[mt], bb[nt][0], bb[nt][1]);
            }
            bsel++; if (bsel == 3) bsel = 0;
        }
    }
    __syncthreads();   // BAR 2: all warps done reading xn; As (G0) visible

    // ---- epilogue1: y = acc + bias -> stmatrix into buf [tok][chan] ----
    {
        float p0[4], p1[4];
#pragma unroll
        for (int nt = 0; nt < 4; nt++) {
            float2 pb = *(const float2*)(bp_ + n0 + nt * 8 + 2 * c4);
            p0[nt] = pb.x; p1[nt] = pb.y;
        }
        const int m  = lane >> 3;                 // matrix index 0..3
        const int rr = (m & 1) * 8 + (lane & 7);  // row within 16
        const int cshift = (m >> 1) * 8;          // +8 cols for matrices 2,3
#pragma unroll
        for (int mt = 0; mt < 4; mt++)
#pragma unroll
            for (int ntp = 0; ntp < 2; ntp++) {
                int nt = 2 * ntp;
                uint32_t addr = buf_u + (uint32_t)(mt * 16 + rr) * BUF_SB +
                                (uint32_t)(n0 + ntp * 16 + cshift) * 2;
                STSM4(addr,
                      h2u(acc[mt][nt][0] + p0[nt],     acc[mt][nt][1] + p1[nt]),
                      h2u(acc[mt][nt][2] + p0[nt],     acc[mt][nt][3] + p1[nt]),
                      h2u(acc[mt][nt+1][0] + p0[nt+1], acc[mt][nt+1][1] + p1[nt+1]),
                      h2u(acc[mt][nt+1][2] + p0[nt+1], acc[mt][nt+1][3] + p1[nt+1]));
            }
    }
    __syncwarp();   // y (own cols) visible warp-wide; no CTA barrier needed

    // ---- GEMM2: z(64x256) = A_w(64x64) @ y ----
#pragma unroll
    for (int mt = 0; mt < 4; mt++)
#pragma unroll
        for (int nt = 0; nt < 4; nt++)
#pragma unroll
            for (int r = 0; r < 4; r++) acc[mt][nt][r] = 0.f;

#pragma unroll
    for (int ks = 0; ks < 4; ks++) {
        uint32_t a[4][4];
        uint32_t abase = as_u + (uint32_t)arow * A_SB + (uint32_t)(ks * 16 + khi) * 2;
#pragma unroll
        for (int mt = 0; mt < 4; mt++)
            LDSM4(a[mt][0], a[mt][1], a[mt][2], a[mt][3],
                  abase + (uint32_t)(mt * 16) * A_SB);
        uint32_t bb[4][2];
#pragma unroll
        for (int ntp = 0; ntp < 2; ntp++) {
            uint32_t baddr = buf_u + (uint32_t)(ks * 16 + tkrow) * BUF_SB +
                             (uint32_t)(n0 + ntp * 16 + tnhi) * 2;
            LDSM4T(bb[2 * ntp][0], bb[2 * ntp][1],
                   bb[2 * ntp + 1][0], bb[2 * ntp + 1][1], baddr);
        }
#pragma unroll
        for (int mt = 0; mt < 4; mt++)
#pragma unroll
            for (int nt = 0; nt < 4; nt++)
                hmma(acc[mt][nt], a[mt], bb[nt][0], bb[nt][1]);
    }

    // ---- epilogue2: direct float2 scatter to gmem (window_reverse) ----
#pragma unroll
    for (int mt = 0; mt < 4; mt++) {
        int t0 = mt * 16 + r4;
        int t1 = t0 + 8;
        float* o0 = out + (size_t)(gbase + (t0 >> 4) * K_ + (t0 & 15)) * EDv;
        float* o1 = out + (size_t)(gbase + (t1 >> 4) * K_ + (t1 & 15)) * EDv;
#pragma unroll
        for (int nt = 0; nt < 4; nt++) {
            int col = n0 + nt * 8 + 2 * c4;
            *(float2*)(o0 + col) = make_float2(acc[mt][nt][0], acc[mt][nt][1]);
            *(float2*)(o1 + col) = make_float2(acc[mt][nt][2], acc[mt][nt][3]);
        }
    }
}

// ---------------------------------------------------------------------------
// Launch
// ---------------------------------------------------------------------------
extern "C" void kernel_launch(void* const* d_in, const int* in_sizes, int n_in,
                              void* d_out, int out_size)
{
    const float* x     = (const float*)d_in[0];
    const float* gamma = (const float*)d_in[1];
    const float* beta  = (const float*)d_in[2];
    const float* Wp    = (const float*)d_in[3];
    const float* bp    = (const float*)d_in[4];
    const float* eb    = (const float*)d_in[5];
    const float* deg   = (const float*)d_in[6];
    float* out = (float*)d_out;

    prep_kernel<<<2 * WTYPES + 64, 256>>>(deg, eb, Wp);

    cudaFuncSetAttribute(fused_fp16,
                         cudaFuncAttributeMaxDynamicSharedMemorySize, SMEM_REQ);
    fused_fp16<<<NWIN, 256, SMEM_REQ>>>(x, gamma, beta, bp, out);
}

// round 14
// speedup vs baseline: 1.7871x; 1.1633x over previous
#include <cuda_runtime.h>
#include <cuda_fp16.h>
#include <cstdint>
#include <cstring>

// Problem constants
#define TPc   4
#define WSZ   16
#define B_    8
#define F_    256
#define K_    64
#define EDv   256
#define NWIN  2048
#define WTYPES 256

// Shared memory layout (byte offsets)
#define OFF_AS  33792     // buf: 64 rows x 528B, then As: 64 rows x 144B
#define SMEM_REQ 43008

#define BUF_S32 132       // buf row stride in b32 (264 halfs); 528B = 33x16B (odd)
#define BUF_SB  528
#define A_SB    144       // As row stride: 64 halfs + 16B pad; 144 = 9x16B (odd)

// Precomputed operands (device globals: no allocation)
// g_Wf: fragment-major fp16 Wp. Layout: [warp(8)][ks(16)][lane(32)][2 x uint4]
//   each uint4 = 4 b32 = the mma B-fragments {bb[nt][h]} for nt pair.
__device__ uint4  g_Wf[8 * 16 * 32 * 2];      // 128 KB
__device__ __half g_Ah[WTYPES * 64 * 64];     // A = deg@eb as fp16 (linear)

// ---------------------------------------------------------------------------
// Prep kernel:
//   blocks [0, 512)   : half of A[w] = deg@eb (fp32 FFMA) -> fp16 linear
//   blocks [512, 640) : Wp -> fragment-major fp16 g_Wf  (block = (w, ks))
// ---------------------------------------------------------------------------
__global__ __launch_bounds__(256) void prep_kernel(
    const float* __restrict__ deg, const float* __restrict__ eb,
    const float* __restrict__ Wp)
{
    __shared__ float Ds[32][64];
    __shared__ float Es[64][68];
    int tid = threadIdx.x;

    if (blockIdx.x >= 2 * WTYPES) {
        // fragment-major Wp: idx -> (w, ks); thread -> (lane l, j)
        int idx = blockIdx.x - 2 * WTYPES;    // 0..127
        int w   = idx >> 4;                   // warp tile (n0 = w*32)
        int ks  = idx & 15;                   // k-step (k16)
        int l   = tid >> 3;                   // lane 0..31
        int j   = tid & 7;                    // fragment reg 0..7
        int nt  = j >> 1;                     // n8-tile 0..3
        int h   = j & 1;                      // b0/b1 (k half)
        int row  = w * 32 + nt * 8 + (l >> 2);
        int colh = ks * 16 + h * 8 + 2 * (l & 3);
        __half2 v = __floats2half2_rn(Wp[row * 256 + colh], Wp[row * 256 + colh + 1]);
        uint32_t u; memcpy(&u, &v, 4);
        ((uint32_t*)g_Wf)[(((size_t)idx) * 32 + l) * 8 + j] = u;
        return;
    }

    int w    = blockIdx.x >> 1;
    int half = blockIdx.x & 1;
    const float* D = deg + (size_t)w * 4096 + half * 32 * 64;
    const float* E = eb  + (size_t)w * 4096;
    for (int idx = tid; idx < 2048; idx += 256)
        Ds[idx >> 6][idx & 63] = D[idx];
    for (int idx = tid; idx < 4096; idx += 256)
        Es[idx >> 6][idx & 63] = E[idx];
    __syncthreads();
    int pr = tid >> 3;                 // local row 0..31
    int q0 = (tid & 7) * 8;
    float acc[8];
#pragma unroll
    for (int j = 0; j < 8; j++) acc[j] = 0.f;
    for (int k = 0; k < 64; k++) {
        float a = Ds[pr][k];
#pragma unroll
        for (int j = 0; j < 8; j++) acc[j] = fmaf(a, Es[k][q0 + j], acc[j]);
    }
    __half* Aout = g_Ah + (size_t)w * 4096 + (half * 32 + pr) * 64 + q0;
#pragma unroll
    for (int j = 0; j < 8; j++) Aout[j] = __float2half_rn(acc[j]);
}

// ---------------------------------------------------------------------------
// mma / ldmatrix / stmatrix / cp.async helpers
// ---------------------------------------------------------------------------
__device__ __forceinline__ uint32_t smem_u32(const void* p) {
    uint32_t a;
    asm("{ .reg .u64 t; cvta.to.shared.u64 t, %1; cvt.u32.u64 %0, t; }" : "=r"(a) : "l"(p));
    return a;
}

#define LDSM4(r0, r1, r2, r3, addr) \
    asm volatile("ldmatrix.sync.aligned.m8n8.x4.shared.b16 {%0,%1,%2,%3}, [%4];" \
                 : "=r"(r0), "=r"(r1), "=r"(r2), "=r"(r3) : "r"(addr))
#define LDSM4T(r0, r1, r2, r3, addr) \
    asm volatile("ldmatrix.sync.aligned.m8n8.x4.trans.shared.b16 {%0,%1,%2,%3}, [%4];" \
                 : "=r"(r0), "=r"(r1), "=r"(r2), "=r"(r3) : "r"(addr))
#define STSM4(addr, r0, r1, r2, r3) \
    asm volatile("stmatrix.sync.aligned.m8n8.x4.shared.b16 [%0], {%1,%2,%3,%4};" \
                 :: "r"(addr), "r"(r0), "r"(r1), "r"(r2), "r"(r3) : "memory")

__device__ __forceinline__ void hmma(float c[4], const uint32_t a[4],
                                     uint32_t b0, uint32_t b1) {
    asm volatile(
        "mma.sync.aligned.m16n8k16.row.col.f32.f16.f16.f32 "
        "{%0,%1,%2,%3}, {%4,%5,%6,%7}, {%8,%9}, {%0,%1,%2,%3};"
        : "+f"(c[0]), "+f"(c[1]), "+f"(c[2]), "+f"(c[3])
        : "r"(a[0]), "r"(a[1]), "r"(a[2]), "r"(a[3]), "r"(b0), "r"(b1));
}

#define CP16(dst, src) \
    asm volatile("cp.async.cg.shared.global [%0], [%1], 16;" :: "r"(dst), "l"(src))
#define CP_COMMIT() asm volatile("cp.async.commit_group;" ::: "memory")
#define CP_WAIT0()  asm volatile("cp.async.wait_group 0;" ::: "memory")

__device__ __forceinline__ uint32_t h2u(float a, float b) {
    __half2 h = __floats2half2_rn(a, b);
    uint32_t u;
    memcpy(&u, &h, 4);
    return u;
}

// ---------------------------------------------------------------------------
// Fused kernel: one 256-thread CTA per window (2 CTAs/SM).
//   GEMM1 B-operand loaded DIRECTLY from fragment-major gmem (g_Wf, L1-resident)
//   -- no smem staging, no B ldmatrix, no waits. x via __ldcg / out via __stcg
//   keep L1 free for g_Wf. Two CTA barriers total.
// ---------------------------------------------------------------------------
__global__ __launch_bounds__(256, 2) void fused_fp16(
    const float* __restrict__ x, const float* __restrict__ gamma,
    const float* __restrict__ beta, const float* __restrict__ bp_,
    float* __restrict__ out)
{
    extern __shared__ char smc[];
    const uint32_t buf_u = smem_u32(smc);
    const uint32_t as_u  = buf_u + OFF_AS;

    const int tid  = threadIdx.x;
    const int lane = tid & 31;
    const int wid  = tid >> 5;
    const int n0   = wid * 32;

    const int n   = blockIdx.x;
    const int b   = n >> 8;
    const int w   = n & 255;
    const int fi  = w >> 2;
    const int nwi = w & 3;
    const int gbase = (b * F_ + fi * TPc) * K_ + nwi * WSZ;

    // ---- prologue: stage As (64 x 128B) via cp.async (2 x 16B per thread) ----
    {
        const char* ahb = (const char*)(g_Ah + (size_t)w * 4096);
#pragma unroll
        for (int i = 0; i < 2; i++) {
            int idx = tid + i * 256;
            int row = idx >> 3, seg = idx & 7;
            CP16(as_u + (uint32_t)(row * A_SB + seg * 16),
                 ahb + (size_t)row * 128 + seg * 16);
        }
        CP_COMMIT();
    }

    // ---- single-pass LayerNorm: warp owns tokens wid*8..+7; params from gmem ----
    {
        float gg[2][4], ee[2][4];
#pragma unroll
        for (int j = 0; j < 2; j++) {
            float4 G = *(const float4*)(gamma + 128 * j + 4 * lane);
            float4 E = *(const float4*)(beta  + 128 * j + 4 * lane);
            gg[j][0] = G.x; gg[j][1] = G.y; gg[j][2] = G.z; gg[j][3] = G.w;
            ee[j][0] = E.x; ee[j][1] = E.y; ee[j][2] = E.z; ee[j][3] = E.w;
        }
        float xv[8][2][4];
#pragma unroll
        for (int t8 = 0; t8 < 8; t8++) {
            int t = wid * 8 + t8;
            const float* xr = x + (size_t)(gbase + (t >> 4) * K_ + (t & 15)) * EDv;
#pragma unroll
            for (int j = 0; j < 2; j++) {
                float4 v = __ldcg((const float4*)(xr + 128 * j + 4 * lane));
                xv[t8][j][0] = v.x; xv[t8][j][1] = v.y;
                xv[t8][j][2] = v.z; xv[t8][j][3] = v.w;
            }
        }
#pragma unroll
        for (int t8 = 0; t8 < 8; t8++) {
            float s = 0.f, ss = 0.f;
#pragma unroll
            for (int j = 0; j < 2; j++)
#pragma unroll
                for (int i = 0; i < 4; i++) {
                    float v = xv[t8][j][i];
                    s += v; ss = fmaf(v, v, ss);
                }
#pragma unroll
            for (int off = 16; off >= 1; off >>= 1) {
                s  += __shfl_xor_sync(0xffffffffu, s, off);
                ss += __shfl_xor_sync(0xffffffffu, ss, off);
            }
            float mu   = s * (1.f / 256.f);
            float var  = ss * (1.f / 256.f) - mu * mu;
            float rstd = rsqrtf(var + 1e-5f);
            int t = wid * 8 + t8;
#pragma unroll
            for (int j = 0; j < 2; j++) {
                uint2 st;
                st.x = h2u((xv[t8][j][0] - mu) * rstd * gg[j][0] + ee[j][0],
                           (xv[t8][j][1] - mu) * rstd * gg[j][1] + ee[j][1]);
                st.y = h2u((xv[t8][j][2] - mu) * rstd * gg[j][2] + ee[j][2],
                           (xv[t8][j][3] - mu) * rstd * gg[j][3] + ee[j][3]);
                *(uint2*)(smc + t * BUF_SB + 256 * j + 8 * lane) = st;
            }
        }
    }
    __syncthreads();   // BAR 1: xn visible to all warps

    const int r4 = lane >> 2, c4 = lane & 3;
    // ldmatrix lane->address parameters
    const int arow  = (lane & 7) + ((lane >> 3) & 1) * 8;  // A row within 16
    const int khi   = (lane >> 4) * 8;                     // +8 halfs (hi-k lanes)
    const int tkrow = ((lane >> 3) & 1) * 8 + (lane & 7);  // trans: k row within 16
    const int tnhi  = (lane >> 4) * 8;                     // trans: n +8

    float acc[4][4][4];
#pragma unroll
    for (int mt = 0; mt < 4; mt++)
#pragma unroll
        for (int nt = 0; nt < 4; nt++)
#pragma unroll
            for (int r = 0; r < 4; r++) acc[mt][nt][r] = 0.f;

    // ---- GEMM1: y(64x256) = xn @ Wp^T; B-frags direct from g_Wf, PF depth 1 ----
    {
        const uint4* __restrict__ wf =
            g_Wf + ((size_t)(wid * 16) * 32 + lane) * 2;   // per-ks stride 64 uint4
        uint4 c0 = __ldg(wf), c1 = __ldg(wf + 1);
#pragma unroll
        for (int ks = 0; ks < 16; ks++) {
            uint4 p0, p1;
            if (ks < 15) {
                p0 = __ldg(wf + (ks + 1) * 64);
                p1 = __ldg(wf + (ks + 1) * 64 + 1);
            }
            uint32_t a[4][4];
            uint32_t abase = buf_u + (uint32_t)arow * BUF_SB +
                             (uint32_t)(ks * 16 + khi) * 2;
#pragma unroll
            for (int mt = 0; mt < 4; mt++)
                LDSM4(a[mt][0], a[mt][1], a[mt][2], a[mt][3],
                      abase + (uint32_t)(mt * 16) * BUF_SB);
#pragma unroll
            for (int mt = 0; mt < 4; mt++) {
                hmma(acc[mt][0], a[mt], c0.x, c0.y);
                hmma(acc[mt][1], a[mt], c0.z, c0.w);
                hmma(acc[mt][2], a[mt], c1.x, c1.y);
                hmma(acc[mt][3], a[mt], c1.z, c1.w);
            }
            c0 = p0; c1 = p1;
        }
    }
    CP_WAIT0();        // As resident (trivially done long ago)
    __syncthreads();   // BAR 2: all warps done reading xn; As visible

    // ---- epilogue1: y = acc + bias -> stmatrix into buf [tok][chan] ----
    {
        float p0[4], p1[4];
#pragma unroll
        for (int nt = 0; nt < 4; nt++) {
            float2 pb = *(const float2*)(bp_ + n0 + nt * 8 + 2 * c4);
            p0[nt] = pb.x; p1[nt] = pb.y;
        }
        const int m  = lane >> 3;                 // matrix index 0..3
        const int rr = (m & 1) * 8 + (lane & 7);  // row within 16
        const int cshift = (m >> 1) * 8;          // +8 cols for matrices 2,3
#pragma unroll
        for (int mt = 0; mt < 4; mt++)
#pragma unroll
            for (int ntp = 0; ntp < 2; ntp++) {
                int nt = 2 * ntp;
                uint32_t addr = buf_u + (uint32_t)(mt * 16 + rr) * BUF_SB +
                                (uint32_t)(n0 + ntp * 16 + cshift) * 2;
                STSM4(addr,
                      h2u(acc[mt][nt][0] + p0[nt],     acc[mt][nt][1] + p1[nt]),
                      h2u(acc[mt][nt][2] + p0[nt],     acc[mt][nt][3] + p1[nt]),
                      h2u(acc[mt][nt+1][0] + p0[nt+1], acc[mt][nt+1][1] + p1[nt+1]),
                      h2u(acc[mt][nt+1][2] + p0[nt+1], acc[mt][nt+1][3] + p1[nt+1]));
            }
    }
    __syncwarp();   // y (own cols) visible warp-wide; no CTA barrier needed

    // ---- GEMM2: z(64x256) = A_w(64x64) @ y ----
#pragma unroll
    for (int mt = 0; mt < 4; mt++)
#pragma unroll
        for (int nt = 0; nt < 4; nt++)
#pragma unroll
            for (int r = 0; r < 4; r++) acc[mt][nt][r] = 0.f;

#pragma unroll
    for (int ks = 0; ks < 4; ks++) {
        uint32_t a[4][4];
        uint32_t abase = as_u + (uint32_t)arow * A_SB + (uint32_t)(ks * 16 + khi) * 2;
#pragma unroll
        for (int mt = 0; mt < 4; mt++)
            LDSM4(a[mt][0], a[mt][1], a[mt][2], a[mt][3],
                  abase + (uint32_t)(mt * 16) * A_SB);
        uint32_t bb[4][2];
#pragma unroll
        for (int ntp = 0; ntp < 2; ntp++) {
            uint32_t baddr = buf_u + (uint32_t)(ks * 16 + tkrow) * BUF_SB +
                             (uint32_t)(n0 + ntp * 16 + tnhi) * 2;
            LDSM4T(bb[2 * ntp][0], bb[2 * ntp][1],
                   bb[2 * ntp + 1][0], bb[2 * ntp + 1][1], baddr);
        }
#pragma unroll
        for (int mt = 0; mt < 4; mt++)
#pragma unroll
            for (int nt = 0; nt < 4; nt++)
                hmma(acc[mt][nt], a[mt], bb[nt][0], bb[nt][1]);
    }

    // ---- epilogue2: direct float2 scatter to gmem (window_reverse), L1-bypass ----
#pragma unroll
    for (int mt = 0; mt < 4; mt++) {
        int t0 = mt * 16 + r4;
        int t1 = t0 + 8;
        float* o0 = out + (size_t)(gbase + (t0 >> 4) * K_ + (t0 & 15)) * EDv;
        float* o1 = out + (size_t)(gbase + (t1 >> 4) * K_ + (t1 & 15)) * EDv;
#pragma unroll
        for (int nt = 0; nt < 4; nt++) {
            int col = n0 + nt * 8 + 2 * c4;
            __stcg((float2*)(o0 + col), make_float2(acc[mt][nt][0], acc[mt][nt][1]));
            __stcg((float2*)(o1 + col), make_float2(acc[mt][nt][2], acc[mt][nt][3]));
        }
    }
}

// ---------------------------------------------------------------------------
// Launch
// ---------------------------------------------------------------------------
extern "C" void kernel_launch(void* const* d_in, const int* in_sizes, int n_in,
                              void* d_out, int out_size)
{
    const float* x     = (const float*)d_in[0];
    const float* gamma = (const float*)d_in[1];
    const float* beta  = (const float*)d_in[2];
    const float* Wp    = (const float*)d_in[3];
    const float* bp    = (const float*)d_in[4];
    const float* eb    = (const float*)d_in[5];
    const float* deg   = (const float*)d_in[6];
    float* out = (float*)d_out;

    prep_kernel<<<2 * WTYPES + 128, 256>>>(deg, eb, Wp);

    cudaFuncSetAttribute(fused_fp16,
                         cudaFuncAttributeMaxDynamicSharedMemorySize, SMEM_REQ);
    fused_fp16<<<NWIN, 256, SMEM_REQ>>>(x, gamma, beta, bp, out);
}

// round 15
// speedup vs baseline: 1.9319x; 1.0810x over previous
#include <cuda_runtime.h>
#include <cuda_fp16.h>
#include <cstdint>
#include <cstring>

// Problem constants
#define TPc   4
#define WSZ   16
#define B_    8
#define F_    256
#define K_    64
#define EDv   256
#define NWIN  2048
#define WTYPES 256

// Shared memory: xn buf only
#define SMEM_REQ 33792
#define BUF_SB  528       // 33x16B (odd) -> ldmatrix conflict-free

// Precomputed fragment-major operands (device globals: no allocation)
// g_WfA: Wp as mma A-fragments (M=chan). [wid(8)][ks(16)][mt(2)][lane(32)] uint4{a0,a1,a2,a3}
__device__ uint4 g_WfA[8 * 16 * 2 * 32];          // 128 KB
// g_Af: A_w as mma A-fragments (M=t_out). [w(256)][ks(4)][mt(4)][lane(32)] uint4
__device__ uint4 g_Af[WTYPES * 4 * 4 * 32];       // 2 MB

__device__ __forceinline__ uint32_t h2u(float a, float b) {
    __half2 h = __floats2half2_rn(a, b);
    uint32_t u;
    memcpy(&u, &h, 4);
    return u;
}

// ---------------------------------------------------------------------------
// Prep kernel:
//   blocks [0,512)    : (w, half) -> 32 rows of A[w]=deg@eb (fp32) -> g_Af frags
//   blocks [512,544)  : Wp -> g_WfA A-fragments
// ---------------------------------------------------------------------------
__global__ __launch_bounds__(256) void prep_kernel(
    const float* __restrict__ deg, const float* __restrict__ eb,
    const float* __restrict__ Wp)
{
    int tid = threadIdx.x;

    if (blockIdx.x >= 2 * WTYPES) {
        // Wp A-fragments: 32 blocks x 256 threads
        int t    = (blockIdx.x - 2 * WTYPES) * 256 + tid;   // 0..8191
        int lane = t & 31;
        int rest = t >> 5;           // 0..255
        int mt   = rest & 1;
        int ks   = (rest >> 1) & 15;
        int wid  = rest >> 5;        // 0..7
        int c0 = wid * 32 + mt * 16 + (lane >> 2);
        int k0 = ks * 16 + 2 * (lane & 3);
        uint4 u;
        u.x = h2u(Wp[c0 * 256 + k0],           Wp[c0 * 256 + k0 + 1]);
        u.y = h2u(Wp[(c0 + 8) * 256 + k0],     Wp[(c0 + 8) * 256 + k0 + 1]);
        u.z = h2u(Wp[c0 * 256 + k0 + 8],       Wp[c0 * 256 + k0 + 9]);
        u.w = h2u(Wp[(c0 + 8) * 256 + k0 + 8], Wp[(c0 + 8) * 256 + k0 + 9]);
        g_WfA[((wid * 16 + ks) * 2 + mt) * 32 + lane] = u;
        return;
    }

    __shared__ float Ds[32][64];
    __shared__ float Es[64][68];
    __shared__ float As[32][68];
    int w = blockIdx.x >> 1;
    int h = blockIdx.x & 1;
    const float* D = deg + (size_t)w * 4096 + h * 32 * 64;
    const float* E = eb  + (size_t)w * 4096;
    for (int idx = tid; idx < 2048; idx += 256)
        Ds[idx >> 6][idx & 63] = D[idx];
    for (int idx = tid; idx < 4096; idx += 256)
        Es[idx >> 6][idx & 63] = E[idx];
    __syncthreads();
    {
        int pr = tid >> 3;               // local row 0..31
        int q0 = (tid & 7) * 8;
        float acc[8];
#pragma unroll
        for (int j = 0; j < 8; j++) acc[j] = 0.f;
        for (int k = 0; k < 64; k++) {
            float a = Ds[pr][k];
#pragma unroll
            for (int j = 0; j < 8; j++) acc[j] = fmaf(a, Es[k][q0 + j], acc[j]);
        }
#pragma unroll
        for (int j = 0; j < 8; j++) As[pr][q0 + j] = acc[j];
    }
    __syncthreads();
    {
        int lane = tid & 31;
        int ks   = (tid >> 5) & 3;
        int mtl  = (tid >> 7) & 1;       // local m-tile (rows mtl*16..)
        int g = lane >> 2, q = lane & 3;
        int r0 = mtl * 16 + g;
        int k0 = ks * 16 + 2 * q;
        uint4 u;
        u.x = h2u(As[r0][k0],         As[r0][k0 + 1]);
        u.y = h2u(As[r0 + 8][k0],     As[r0 + 8][k0 + 1]);
        u.z = h2u(As[r0][k0 + 8],     As[r0][k0 + 9]);
        u.w = h2u(As[r0 + 8][k0 + 8], As[r0 + 8][k0 + 9]);
        int mt = h * 2 + mtl;            // global m-tile 0..3
        g_Af[((w * 4 + ks) * 4 + mt) * 32 + lane] = u;
    }
}

// ---------------------------------------------------------------------------
// mma / ldmatrix helpers
// ---------------------------------------------------------------------------
__device__ __forceinline__ uint32_t smem_u32(const void* p) {
    uint32_t a;
    asm("{ .reg .u64 t; cvta.to.shared.u64 t, %1; cvt.u32.u64 %0, t; }" : "=r"(a) : "l"(p));
    return a;
}

#define LDSM4(r0, r1, r2, r3, addr) \
    asm volatile("ldmatrix.sync.aligned.m8n8.x4.shared.b16 {%0,%1,%2,%3}, [%4];" \
                 : "=r"(r0), "=r"(r1), "=r"(r2), "=r"(r3) : "r"(addr))

__device__ __forceinline__ void hmma(float c[4], const uint32_t a[4],
                                     uint32_t b0, uint32_t b1) {
    asm volatile(
        "mma.sync.aligned.m16n8k16.row.col.f32.f16.f16.f32 "
        "{%0,%1,%2,%3}, {%4,%5,%6,%7}, {%8,%9}, {%0,%1,%2,%3};"
        : "+f"(c[0]), "+f"(c[1]), "+f"(c[2]), "+f"(c[3])
        : "r"(a[0]), "r"(a[1]), "r"(a[2]), "r"(a[3]), "r"(b0), "r"(b1));
}

// ---------------------------------------------------------------------------
// Fused kernel: one 256-thread CTA per window (2 CTAs/SM).
//   GEMM1 (y^T = Wp @ xn^T): A = Wp frags direct LDG, B = xn LDSM from smem.
//   y^T C-frags convert IN REGISTERS to GEMM2 B-frags (bias + fp16).
//   GEMM2 (z = A_w @ y): A = A_w frags direct LDG, B = registers.
//   ONE CTA barrier total (post-LN); warps fully independent after it.
// ---------------------------------------------------------------------------
__global__ __launch_bounds__(256, 2) void fused_fp16(
    const float* __restrict__ x, const float* __restrict__ gamma,
    const float* __restrict__ beta, const float* __restrict__ bp_,
    float* __restrict__ out)
{
    extern __shared__ char smc[];
    const uint32_t buf_u = smem_u32(smc);

    const int tid  = threadIdx.x;
    const int lane = tid & 31;
    const int wid  = tid >> 5;
    const int n0   = wid * 32;       // this warp's 32 channels

    const int n   = blockIdx.x;
    const int b   = n >> 8;
    const int w   = n & 255;
    const int fi  = w >> 2;
    const int nwi = w & 3;
    const int gbase = (b * F_ + fi * TPc) * K_ + nwi * WSZ;

    // ---- single-pass LayerNorm: warp owns tokens wid*8..+7; params from gmem ----
    {
        float gg[2][4], ee[2][4];
#pragma unroll
        for (int j = 0; j < 2; j++) {
            float4 G = *(const float4*)(gamma + 128 * j + 4 * lane);
            float4 E = *(const float4*)(beta  + 128 * j + 4 * lane);
            gg[j][0] = G.x; gg[j][1] = G.y; gg[j][2] = G.z; gg[j][3] = G.w;
            ee[j][0] = E.x; ee[j][1] = E.y; ee[j][2] = E.z; ee[j][3] = E.w;
        }
        float xv[8][2][4];
#pragma unroll
        for (int t8 = 0; t8 < 8; t8++) {
            int t = wid * 8 + t8;
            const float* xr = x + (size_t)(gbase + (t >> 4) * K_ + (t & 15)) * EDv;
#pragma unroll
            for (int j = 0; j < 2; j++) {
                float4 v = __ldcg((const float4*)(xr + 128 * j + 4 * lane));
                xv[t8][j][0] = v.x; xv[t8][j][1] = v.y;
                xv[t8][j][2] = v.z; xv[t8][j][3] = v.w;
            }
        }
#pragma unroll
        for (int t8 = 0; t8 < 8; t8++) {
            float s = 0.f, ss = 0.f;
#pragma unroll
            for (int j = 0; j < 2; j++)
#pragma unroll
                for (int i = 0; i < 4; i++) {
                    float v = xv[t8][j][i];
                    s += v; ss = fmaf(v, v, ss);
                }
#pragma unroll
            for (int off = 16; off >= 1; off >>= 1) {
                s  += __shfl_xor_sync(0xffffffffu, s, off);
                ss += __shfl_xor_sync(0xffffffffu, ss, off);
            }
            float mu   = s * (1.f / 256.f);
            float var  = ss * (1.f / 256.f) - mu * mu;
            float rstd = rsqrtf(var + 1e-5f);
            int t = wid * 8 + t8;
#pragma unroll
            for (int j = 0; j < 2; j++) {
                uint2 st;
                st.x = h2u((xv[t8][j][0] - mu) * rstd * gg[j][0] + ee[j][0],
                           (xv[t8][j][1] - mu) * rstd * gg[j][1] + ee[j][1]);
                st.y = h2u((xv[t8][j][2] - mu) * rstd * gg[j][2] + ee[j][2],
                           (xv[t8][j][3] - mu) * rstd * gg[j][3] + ee[j][3]);
                *(uint2*)(smc + t * BUF_SB + 256 * j + 8 * lane) = st;
            }
        }
    }
    __syncthreads();   // THE ONLY CTA BARRIER: xn visible to all warps

    const int r4 = lane >> 2, c4 = lane & 3;
    // ldmatrix B-path lane->address parameters (token rows, k halves)
    const int bnrow = ((lane >> 4) & 1) * 8 + (lane & 7);
    const int bkhi  = ((lane >> 3) & 1) * 8;

    // ---- GEMM1: y^T(256chan x 64tok) slice = Wp(A-frags LDG) @ xn^T(B LDSM) ----
    float acc1[2][8][4];
#pragma unroll
    for (int mt = 0; mt < 2; mt++)
#pragma unroll
        for (int nt = 0; nt < 8; nt++)
#pragma unroll
            for (int r = 0; r < 4; r++) acc1[mt][nt][r] = 0.f;

    {
        uint32_t aC[2][4], aN[2][4];
#pragma unroll
        for (int mt = 0; mt < 2; mt++)
            *(uint4*)aC[mt] = __ldg(g_WfA + ((wid * 16 + 0) * 2 + mt) * 32 + lane);
#pragma unroll
        for (int ks = 0; ks < 16; ks++) {
            if (ks < 15) {
#pragma unroll
                for (int mt = 0; mt < 2; mt++)
                    *(uint4*)aN[mt] =
                        __ldg(g_WfA + ((wid * 16 + ks + 1) * 2 + mt) * 32 + lane);
            }
#pragma unroll
            for (int ntp = 0; ntp < 4; ntp++) {
                uint32_t r0, r1, r2, r3;
                uint32_t baddr = buf_u + (uint32_t)(ntp * 16 + bnrow) * BUF_SB +
                                 (uint32_t)(ks * 16 + bkhi) * 2;
                LDSM4(r0, r1, r2, r3, baddr);
#pragma unroll
                for (int mt = 0; mt < 2; mt++) {
                    hmma(acc1[mt][2 * ntp],     aC[mt], r0, r1);
                    hmma(acc1[mt][2 * ntp + 1], aC[mt], r2, r3);
                }
            }
#pragma unroll
            for (int mt = 0; mt < 2; mt++)
#pragma unroll
                for (int r = 0; r < 4; r++) aC[mt][r] = aN[mt][r];
        }
    }

    // ---- convert: y^T C-frags + bias -> GEMM2 B-frags (registers only) ----
    uint32_t yb[4][4][2];   // [chan-tile ntc][ks][b0,b1]
    {
        float bb[4];
#pragma unroll
        for (int ntc = 0; ntc < 4; ntc++)
            bb[ntc] = __ldg(bp_ + n0 + ntc * 8 + r4);
#pragma unroll
        for (int ntc = 0; ntc < 4; ntc++) {
            int mt1 = ntc >> 1;
            int h2i = (ntc & 1) * 2;
#pragma unroll
            for (int ks = 0; ks < 4; ks++) {
                yb[ntc][ks][0] = h2u(acc1[mt1][2 * ks][h2i]     + bb[ntc],
                                     acc1[mt1][2 * ks][h2i + 1] + bb[ntc]);
                yb[ntc][ks][1] = h2u(acc1[mt1][2 * ks + 1][h2i]     + bb[ntc],
                                     acc1[mt1][2 * ks + 1][h2i + 1] + bb[ntc]);
            }
        }
    }

    // ---- GEMM2: z(64tok x 32chan slice) = A_w(A-frags LDG) @ y(registers) ----
    float acc2[4][4][4];
#pragma unroll
    for (int mt = 0; mt < 4; mt++)
#pragma unroll
        for (int nt = 0; nt < 4; nt++)
#pragma unroll
            for (int r = 0; r < 4; r++) acc2[mt][nt][r] = 0.f;

#pragma unroll
    for (int ks = 0; ks < 4; ks++) {
        uint32_t a2[4][4];
#pragma unroll
        for (int mt = 0; mt < 4; mt++)
            *(uint4*)a2[mt] = __ldg(g_Af + (((size_t)w * 4 + ks) * 4 + mt) * 32 + lane);
#pragma unroll
        for (int mt = 0; mt < 4; mt++)
#pragma unroll
            for (int ntc = 0; ntc < 4; ntc++)
                hmma(acc2[mt][ntc], a2[mt], yb[ntc][ks][0], yb[ntc][ks][1]);
    }

    // ---- epilogue: direct float2 scatter to gmem (window_reverse) ----
#pragma unroll
    for (int mt = 0; mt < 4; mt++) {
        int t0 = mt * 16 + r4;
        int t1 = t0 + 8;
        float* o0 = out + (size_t)(gbase + (t0 >> 4) * K_ + (t0 & 15)) * EDv;
        float* o1 = out + (size_t)(gbase + (t1 >> 4) * K_ + (t1 & 15)) * EDv;
#pragma unroll
        for (int nt = 0; nt < 4; nt++) {
            int col = n0 + nt * 8 + 2 * c4;
            __stcg((float2*)(o0 + col), make_float2(acc2[mt][nt][0], acc2[mt][nt][1]));
            __stcg((float2*)(o1 + col), make_float2(acc2[mt][nt][2], acc2[mt][nt][3]));
        }
    }
}

// ---------------------------------------------------------------------------
// Launch
// ---------------------------------------------------------------------------
extern "C" void kernel_launch(void* const* d_in, const int* in_sizes, int n_in,
                              void* d_out, int out_size)
{
    const float* x     = (const float*)d_in[0];
    const float* gamma = (const float*)d_in[1];
    const float* beta  = (const float*)d_in[2];
    const float* Wp    = (const float*)d_in[3];
    const float* bp    = (const float*)d_in[4];
    const float* eb    = (const float*)d_in[5];
    const float* deg   = (const float*)d_in[6];
    float* out = (float*)d_out;

    prep_kernel<<<2 * WTYPES + 32, 256>>>(deg, eb, Wp);

    cudaFuncSetAttribute(fused_fp16,
                         cudaFuncAttributeMaxDynamicSharedMemorySize, SMEM_REQ);
    fused_fp16<<<NWIN, 256, SMEM_REQ>>>(x, gamma, beta, bp, out);
}